// round 1
// baseline (speedup 1.0000x reference)
#include <cuda_runtime.h>
#include <math.h>

#define Nn 10000
#define Ee 320000
#define Dd 256
#define Hh 4
#define DKk 64
#define BN_EPS 1e-5f

// ---------------- scratch (device globals: no allocation allowed) ----------------
__device__ float g_deg[Nn];
__device__ float g_smax;
__device__ float g_ssum;
__device__ float g_mV[Nn * Dd];
__device__ float g_q[Nn * Dd];
__device__ float g_k[Nn * Dd];
__device__ float g_vv[Nn * Dd];
__device__ float g_wv[Nn * Dd];
__device__ float g_z[Nn * Hh];
__device__ float g_o[Nn * Dd];
__device__ float g_bnsum[Dd];
__device__ float g_bnss[Dd];

// ---------------- 0: zero scratch ----------------
__global__ void k_zero() {
    int i = blockIdx.x * blockDim.x + threadIdx.x;
    if (i < Nn * Dd) g_wv[i] = 0.0f;
    if (i < Nn) g_deg[i] = 0.0f;
    if (i < Nn * Hh) g_z[i] = 0.0f;
    if (i < Dd) { g_bnsum[i] = 0.0f; g_bnss[i] = 0.0f; }
}

// ---------------- 1: degree counts ----------------
__global__ void k_degree(const int* __restrict__ src, const int* __restrict__ dst) {
    int e = blockIdx.x * blockDim.x + threadIdx.x;
    if (e < Ee) {
        atomicAdd(&g_deg[src[e]], 1.0f);
        atomicAdd(&g_deg[dst[e]], 1.0f);
    }
}

// ---------------- 2: softmax(deg) reduction (max + sum of exp) ----------------
__global__ void k_softmax_reduce() {
    __shared__ float red[1024];
    int t = threadIdx.x;
    float m = -1e30f;
    for (int i = t; i < Nn; i += 1024) m = fmaxf(m, g_deg[i]);
    red[t] = m; __syncthreads();
    for (int s = 512; s > 0; s >>= 1) {
        if (t < s) red[t] = fmaxf(red[t], red[t + s]);
        __syncthreads();
    }
    float gm = red[0];
    __syncthreads();
    float sum = 0.0f;
    for (int i = t; i < Nn; i += 1024) sum += expf(g_deg[i] - gm);
    red[t] = sum; __syncthreads();
    for (int s = 512; s > 0; s >>= 1) {
        if (t < s) red[t] += red[t + s];
        __syncthreads();
    }
    if (t == 0) { g_smax = gm; g_ssum = red[0]; }
}

// ---------------- 3: mV = v * center[n] ----------------
__global__ void k_mv(const float* __restrict__ v) {
    int i4 = blockIdx.x * blockDim.x + threadIdx.x;
    if (i4 >= Nn * Dd / 4) return;
    int n = i4 / (Dd / 4);
    float c = expf(g_deg[n] - g_smax) / g_ssum;
    float4 a = ((const float4*)v)[i4];
    a.x *= c; a.y *= c; a.z *= c; a.w *= c;
    ((float4*)g_mV)[i4] = a;
}

// ---------------- 4: tiled fp32 GEMM  C[M,256] = A[M,256] @ W[256,256] + bias ----------------
// MODE: 0 -> C=g_q, A=g_mV ; 1 -> C=g_k ; 2 -> C=g_vv ; 3 -> A=g_wv/z, C=g_o
template <int MODE>
__global__ void __launch_bounds__(256) k_gemm(const float* __restrict__ W,
                                              const float* __restrict__ bias) {
    const float* A = (MODE == 3) ? g_wv : g_mV;
    float* C = (MODE == 0) ? g_q : (MODE == 1) ? g_k : (MODE == 2) ? g_vv : g_o;

    __shared__ float As[8][128];
    __shared__ float Bs[8][128];
    const int tid = threadIdx.x;
    const int bm = blockIdx.y * 128;
    const int bn = blockIdx.x * 128;
    const int arow = tid >> 1, acol = (tid & 1) << 2;   // A tile: 128 x 8
    const int brow = tid >> 5, bcol = (tid & 31) << 2;  // B tile: 8 x 128
    const int ty = tid >> 4, tx = tid & 15;

    float acc[8][8];
#pragma unroll
    for (int i = 0; i < 8; i++)
#pragma unroll
        for (int j = 0; j < 8; j++) acc[i][j] = 0.0f;

    for (int k0 = 0; k0 < Dd; k0 += 8) {
        int gr = bm + arow;
        float4 a4 = make_float4(0.f, 0.f, 0.f, 0.f);
        if (gr < Nn) {
            a4 = *(const float4*)(A + (size_t)gr * Dd + k0 + acol);
            if (MODE == 3) {
                float inv = 1.0f / g_z[gr * Hh + ((k0 + acol) >> 6)];
                a4.x *= inv; a4.y *= inv; a4.z *= inv; a4.w *= inv;
            }
        }
        As[acol + 0][arow] = a4.x;
        As[acol + 1][arow] = a4.y;
        As[acol + 2][arow] = a4.z;
        As[acol + 3][arow] = a4.w;
        *(float4*)&Bs[brow][bcol] =
            *(const float4*)(W + (size_t)(k0 + brow) * Dd + bn + bcol);
        __syncthreads();
#pragma unroll
        for (int kk = 0; kk < 8; kk++) {
            float ar[8], br[8];
            *(float4*)(ar)     = *(float4*)&As[kk][ty * 8];
            *(float4*)(ar + 4) = *(float4*)&As[kk][ty * 8 + 4];
            *(float4*)(br)     = *(float4*)&Bs[kk][tx * 8];
            *(float4*)(br + 4) = *(float4*)&Bs[kk][tx * 8 + 4];
#pragma unroll
            for (int i = 0; i < 8; i++)
#pragma unroll
                for (int j = 0; j < 8; j++) acc[i][j] = fmaf(ar[i], br[j], acc[i][j]);
        }
        __syncthreads();
    }
#pragma unroll
    for (int i = 0; i < 8; i++) {
        int gr = bm + ty * 8 + i;
        if (gr >= Nn) continue;
#pragma unroll
        for (int j = 0; j < 8; j += 4) {
            int gc = bn + tx * 8 + j;
            float4 o4;
            o4.x = acc[i][j]     + bias[gc];
            o4.y = acc[i][j + 1] + bias[gc + 1];
            o4.z = acc[i][j + 2] + bias[gc + 2];
            o4.w = acc[i][j + 3] + bias[gc + 3];
            *(float4*)(C + (size_t)gr * Dd + gc) = o4;
        }
    }
}

// ---------------- 5: edge scores + z + wv scatter (one warp per edge) ----------------
__global__ void k_edge(const int* __restrict__ src, const int* __restrict__ dst) {
    int gw = (blockIdx.x * blockDim.x + threadIdx.x) >> 5;
    int lane = threadIdx.x & 31;
    if (gw >= Ee) return;
    int s0 = src[gw], d0 = dst[gw];
    const float4* kr = (const float4*)(g_k + (size_t)s0 * Dd);
    const float4* qr = (const float4*)(g_q + (size_t)d0 * Dd);
    float4 a0 = kr[lane * 2], a1 = kr[lane * 2 + 1];
    float4 b0 = qr[lane * 2], b1 = qr[lane * 2 + 1];
    float dot = a0.x * b0.x + a0.y * b0.y + a0.z * b0.z + a0.w * b0.w +
                a1.x * b1.x + a1.y * b1.y + a1.z * b1.z + a1.w * b1.w;
    // reduce within 8-lane groups (one head per group)
    dot += __shfl_down_sync(0xffffffffu, dot, 4, 8);
    dot += __shfl_down_sync(0xffffffffu, dot, 2, 8);
    dot += __shfl_down_sync(0xffffffffu, dot, 1, 8);
    float sv = 0.0f;
    if ((lane & 7) == 0) {
        float sc = fminf(fmaxf(dot * 0.125f, -5.0f), 5.0f);
        sv = expf(sc);
        atomicAdd(&g_z[d0 * Hh + (lane >> 3)], sv);
    }
    sv = __shfl_sync(0xffffffffu, sv, 0, 8);
    const float4* vr = (const float4*)(g_vv + (size_t)s0 * Dd);
    float4 v0 = vr[lane * 2], v1 = vr[lane * 2 + 1];
    float* wout = g_wv + (size_t)d0 * Dd + lane * 8;
    atomicAdd(wout + 0, v0.x * sv);
    atomicAdd(wout + 1, v0.y * sv);
    atomicAdd(wout + 2, v0.z * sv);
    atomicAdd(wout + 3, v0.w * sv);
    atomicAdd(wout + 4, v1.x * sv);
    atomicAdd(wout + 5, v1.y * sv);
    atomicAdd(wout + 6, v1.z * sv);
    atomicAdd(wout + 7, v1.w * sv);
}

// ---------------- 6: BatchNorm column statistics (sum, sumsq) ----------------
__global__ void k_bnstat() {
    int t = threadIdx.x;  // column 0..255
    int r0 = blockIdx.x * 40;
    float s = 0.0f, ss = 0.0f;
    for (int r = r0; r < r0 + 40; r++) {
        float val = g_o[(size_t)r * Dd + t];
        s += val;
        ss = fmaf(val, val, ss);
    }
    atomicAdd(&g_bnsum[t], s);
    atomicAdd(&g_bnss[t], ss);
}

// ---------------- 7: fused BN-apply + ReLU6 + SE block + hardswish + residual ----------------
__global__ void __launch_bounds__(256) k_se(const float* __restrict__ gamma,
                                            const float* __restrict__ beta,
                                            const float* __restrict__ W1,
                                            const float* __restrict__ b1,
                                            const float* __restrict__ W2,
                                            const float* __restrict__ b2,
                                            const float* __restrict__ v,
                                            float* __restrict__ out) {
    __shared__ float xs[16][256];
    __shared__ float hs[16][64];
    __shared__ float sa[256], sb[256];
    int t = threadIdx.x;
    int row0 = blockIdx.x * 16;

    {   // per-column affine from batch stats
        float mean = g_bnsum[t] * (1.0f / Nn);
        float var = g_bnss[t] * (1.0f / Nn) - mean * mean;
        float istd = rsqrtf(var + BN_EPS);
        float a = gamma[t] * istd;
        sa[t] = a;
        sb[t] = beta[t] - mean * a;
    }
    __syncthreads();

    // x = relu6(a*o + b) into smem
    for (int i = t; i < 16 * 256; i += 256) {
        int r = i >> 8, c = i & 255;
        float xv = fmaf(sa[c], g_o[(size_t)(row0 + r) * Dd + c], sb[c]);
        xs[r][c] = fminf(fmaxf(xv, 0.0f), 6.0f);
    }
    __syncthreads();

    // h = relu6(x @ W1 + b1): thread -> (hc = t&63, 4 rows)
    {
        int hc = t & 63, rg = t >> 6;
        float acc0 = b1[hc], acc1 = acc0, acc2 = acc0, acc3 = acc0;
        for (int k = 0; k < 256; k++) {
            float w = W1[k * 64 + hc];
            acc0 = fmaf(xs[rg * 4 + 0][k], w, acc0);
            acc1 = fmaf(xs[rg * 4 + 1][k], w, acc1);
            acc2 = fmaf(xs[rg * 4 + 2][k], w, acc2);
            acc3 = fmaf(xs[rg * 4 + 3][k], w, acc3);
        }
        hs[rg * 4 + 0][hc] = fminf(fmaxf(acc0, 0.0f), 6.0f);
        hs[rg * 4 + 1][hc] = fminf(fmaxf(acc1, 0.0f), 6.0f);
        hs[rg * 4 + 2][hc] = fminf(fmaxf(acc2, 0.0f), 6.0f);
        hs[rg * 4 + 3][hc] = fminf(fmaxf(acc3, 0.0f), 6.0f);
    }
    __syncthreads();

    // se = h @ W2 + b2 ; out = hardswish(se) * x + v
    {
        int col = t;
        float acc[16];
        float bb = b2[col];
#pragma unroll
        for (int r = 0; r < 16; r++) acc[r] = bb;
        for (int k = 0; k < 64; k++) {
            float w = W2[k * 256 + col];
#pragma unroll
            for (int r = 0; r < 16; r++) acc[r] = fmaf(hs[r][k], w, acc[r]);
        }
#pragma unroll
        for (int r = 0; r < 16; r++) {
            float u = acc[r];
            float act = u * __saturatef((u + 3.0f) * (1.0f / 6.0f));
            size_t idx = (size_t)(row0 + r) * Dd + col;
            out[idx] = fmaf(act, xs[r][col], v[idx]);
        }
    }
}

// ---------------- launch ----------------
extern "C" void kernel_launch(void* const* d_in, const int* in_sizes, int n_in,
                              void* d_out, int out_size) {
    const float* v     = (const float*)d_in[0];
    const float* WQ    = (const float*)d_in[1];
    const float* bQ    = (const float*)d_in[2];
    const float* WK    = (const float*)d_in[3];
    const float* bK    = (const float*)d_in[4];
    const float* WV    = (const float*)d_in[5];
    const float* bV    = (const float*)d_in[6];
    const float* Wo    = (const float*)d_in[7];
    const float* bo    = (const float*)d_in[8];
    const float* W1    = (const float*)d_in[9];
    const float* b1    = (const float*)d_in[10];
    const float* W2    = (const float*)d_in[11];
    const float* b2    = (const float*)d_in[12];
    const float* gamma = (const float*)d_in[13];
    const float* beta  = (const float*)d_in[14];
    const int*   src   = (const int*)d_in[15];
    const int*   dst   = (const int*)d_in[16];
    float* out = (float*)d_out;

    k_zero<<<(Nn * Dd + 255) / 256, 256>>>();
    k_degree<<<(Ee + 255) / 256, 256>>>(src, dst);
    k_softmax_reduce<<<1, 1024>>>();
    k_mv<<<(Nn * Dd / 4 + 255) / 256, 256>>>(v);

    dim3 gg(2, (Nn + 127) / 128);
    k_gemm<0><<<gg, 256>>>(WQ, bQ);
    k_gemm<1><<<gg, 256>>>(WK, bK);
    k_gemm<2><<<gg, 256>>>(WV, bV);

    k_edge<<<(Ee * 32 + 255) / 256, 256>>>(src, dst);

    k_gemm<3><<<gg, 256>>>(Wo, bo);

    k_bnstat<<<Nn / 40, 256>>>();
    k_se<<<Nn / 16, 256>>>(gamma, beta, W1, b1, W2, b2, v, out);
}

// round 2
// speedup vs baseline: 2.7716x; 2.7716x over previous
#include <cuda_runtime.h>
#include <math.h>

#define Nn 10000
#define Ee 320000
#define Dd 256
#define Hh 4
#define BN_EPS 1e-5f
#define MPAD 10112   // 79 * 128, padded row length for transposed activations

// ---------------- scratch (device globals) ----------------
__device__ float g_deg[Nn];
__device__ float g_smax;
__device__ float g_ssum;
__device__ float g_mVT[Dd * MPAD];   // transposed, center-scaled mV
__device__ float g_q[Nn * Dd];
__device__ float g_k[Nn * Dd];
__device__ float g_vv[Nn * Dd];
__device__ float g_wv[Nn * Dd];
__device__ float g_wvT[Dd * MPAD];   // transposed wv / z
__device__ float g_z[Nn * Hh];
__device__ float g_o[Nn * Dd];
__device__ float g_bnsum[Dd];
__device__ float g_bnss[Dd];

// ---------------- 0: zero scratch ----------------
__global__ void k_zero() {
    int i = blockIdx.x * blockDim.x + threadIdx.x;
    if (i < Nn * Dd) g_wv[i] = 0.0f;
    if (i < Nn) g_deg[i] = 0.0f;
    if (i < Nn * Hh) g_z[i] = 0.0f;
    if (i < Dd) { g_bnsum[i] = 0.0f; g_bnss[i] = 0.0f; }
}

// ---------------- 1: degree counts ----------------
__global__ void k_degree(const int* __restrict__ src, const int* __restrict__ dst) {
    int e = blockIdx.x * blockDim.x + threadIdx.x;
    if (e < Ee) {
        atomicAdd(&g_deg[src[e]], 1.0f);
        atomicAdd(&g_deg[dst[e]], 1.0f);
    }
}

// ---------------- 2: softmax(deg) reduction ----------------
__global__ void k_softmax_reduce() {
    __shared__ float red[1024];
    int t = threadIdx.x;
    float m = -1e30f;
    for (int i = t; i < Nn; i += 1024) m = fmaxf(m, g_deg[i]);
    red[t] = m; __syncthreads();
    for (int s = 512; s > 0; s >>= 1) {
        if (t < s) red[t] = fmaxf(red[t], red[t + s]);
        __syncthreads();
    }
    float gm = red[0];
    __syncthreads();
    float sum = 0.0f;
    for (int i = t; i < Nn; i += 1024) sum += expf(g_deg[i] - gm);
    red[t] = sum; __syncthreads();
    for (int s = 512; s > 0; s >>= 1) {
        if (t < s) red[t] += red[t + s];
        __syncthreads();
    }
    if (t == 0) { g_smax = gm; g_ssum = red[0]; }
}

// ---------------- 3: mVT[d][n] = v[n][d] * center[n]  (tiled transpose) ----------------
__global__ void k_mvT(const float* __restrict__ v) {
    __shared__ float tile[32][33];
    int d0 = blockIdx.x * 32;
    int n0 = blockIdx.y * 32;
    int tx = threadIdx.x, ty = threadIdx.y;
#pragma unroll
    for (int j = 0; j < 32; j += 8) {
        int n = n0 + ty + j;
        float val = 0.0f;
        if (n < Nn) {
            float c = expf(g_deg[n] - g_smax) / g_ssum;
            val = v[(size_t)n * Dd + d0 + tx] * c;
        }
        tile[ty + j][tx] = val;
    }
    __syncthreads();
#pragma unroll
    for (int j = 0; j < 32; j += 8) {
        int d = d0 + ty + j;
        g_mVT[(size_t)d * MPAD + n0 + tx] = tile[tx][ty + j];
    }
}

// ---------------- 3b: wvT[d][n] = wv[n][d] / z[n][d>>6] ----------------
__global__ void k_wvT() {
    __shared__ float tile[32][33];
    int d0 = blockIdx.x * 32;
    int n0 = blockIdx.y * 32;
    int tx = threadIdx.x, ty = threadIdx.y;
    int d_of_tx = d0 + tx;
#pragma unroll
    for (int j = 0; j < 32; j += 8) {
        int n = n0 + ty + j;
        float val = 0.0f;
        if (n < Nn) {
            val = g_wv[(size_t)n * Dd + d_of_tx] / g_z[n * Hh + (d_of_tx >> 6)];
        }
        tile[ty + j][tx] = val;
    }
    __syncthreads();
#pragma unroll
    for (int j = 0; j < 32; j += 8) {
        int d = d0 + ty + j;
        g_wvT[(size_t)d * MPAD + n0 + tx] = tile[tx][ty + j];
    }
}

// ---------------- tf32 helpers ----------------
__device__ __forceinline__ unsigned cvt_tf32(float f) {
    unsigned u;
    asm("cvt.rna.tf32.f32 %0, %1;" : "=r"(u) : "f"(f));
    return u;
}

__device__ __forceinline__ void mma8(float* c, const unsigned* a, const unsigned* b) {
    asm volatile(
        "mma.sync.aligned.m16n8k8.row.col.f32.tf32.tf32.f32 "
        "{%0,%1,%2,%3},{%4,%5,%6,%7},{%8,%9},{%0,%1,%2,%3};"
        : "+f"(c[0]), "+f"(c[1]), "+f"(c[2]), "+f"(c[3])
        : "r"(a[0]), "r"(a[1]), "r"(a[2]), "r"(a[3]), "r"(b[0]), "r"(b[1]));
}

// ---------------- 4: tf32 tensor-core GEMM  C[M,256] = A[M,256] @ W[256,256] + bias
// MODE 0: A = mVT, z-dim selects (WQ->g_q, WK->g_k, WV->g_vv)
// MODE 1: A = wvT, C = g_o
template <int MODE>
__global__ void __launch_bounds__(256) k_gemm_tc(
    const float* __restrict__ Wa, const float* __restrict__ Wb, const float* __restrict__ Wc,
    const float* __restrict__ ba, const float* __restrict__ bb, const float* __restrict__ bc) {
    const float* AT;
    const float* W;
    const float* bias;
    float* C;
    if (MODE == 0) {
        AT = g_mVT;
        int z = blockIdx.z;
        W = (z == 0) ? Wa : (z == 1) ? Wb : Wc;
        bias = (z == 0) ? ba : (z == 1) ? bb : bc;
        C = (z == 0) ? g_q : (z == 1) ? g_k : g_vv;
    } else {
        AT = g_wvT; W = Wa; bias = ba; C = g_o;
    }

    __shared__ unsigned As[32][136];   // [k][m], stride 136 -> conflict-free frag loads
    __shared__ unsigned Bs[32][136];   // [k][n]

    const int tid = threadIdx.x;
    const int lane = tid & 31;
    const int warp = tid >> 5;
    const int wm = warp & 1;          // 2 warps along M (64 rows each)
    const int wn = warp >> 1;         // 4 warps along N (32 cols each)
    const int bm = blockIdx.y * 128;
    const int bn = blockIdx.x * 128;
    const int r = lane >> 2;
    const int t = lane & 3;

    float acc[4][4][4];
#pragma unroll
    for (int i = 0; i < 4; i++)
#pragma unroll
        for (int j = 0; j < 4; j++)
#pragma unroll
            for (int q = 0; q < 4; q++) acc[i][j][q] = 0.0f;

    for (int k0 = 0; k0 < Dd; k0 += 32) {
        // stage A (32x128) and B (32x128), tf32-converted
#pragma unroll
        for (int i = 0; i < 4; i++) {
            int idx = tid + i * 256;            // 0..1023 float4 slots
            int kr = idx >> 5;                  // 0..31
            int mc = (idx & 31) << 2;           // 0..124
            float4 a = *(const float4*)(AT + (size_t)(k0 + kr) * MPAD + bm + mc);
            uint4 ua;
            ua.x = cvt_tf32(a.x); ua.y = cvt_tf32(a.y);
            ua.z = cvt_tf32(a.z); ua.w = cvt_tf32(a.w);
            *(uint4*)&As[kr][mc] = ua;
            float4 b = *(const float4*)(W + (size_t)(k0 + kr) * Dd + bn + mc);
            uint4 ub;
            ub.x = cvt_tf32(b.x); ub.y = cvt_tf32(b.y);
            ub.z = cvt_tf32(b.z); ub.w = cvt_tf32(b.w);
            *(uint4*)&Bs[kr][mc] = ub;
        }
        __syncthreads();
#pragma unroll
        for (int kk = 0; kk < 32; kk += 8) {
            unsigned af[4][4];
#pragma unroll
            for (int fm = 0; fm < 4; fm++) {
                int m = wm * 64 + fm * 16 + r;
                af[fm][0] = As[kk + t][m];
                af[fm][1] = As[kk + t][m + 8];
                af[fm][2] = As[kk + t + 4][m];
                af[fm][3] = As[kk + t + 4][m + 8];
            }
            unsigned bf[4][2];
#pragma unroll
            for (int fn = 0; fn < 4; fn++) {
                int n = wn * 32 + fn * 8 + r;
                bf[fn][0] = Bs[kk + t][n];
                bf[fn][1] = Bs[kk + t + 4][n];
            }
#pragma unroll
            for (int fm = 0; fm < 4; fm++)
#pragma unroll
                for (int fn = 0; fn < 4; fn++)
                    mma8(acc[fm][fn], af[fm], bf[fn]);
        }
        __syncthreads();
    }

    // epilogue: c0:(r,2t) c1:(r,2t+1) c2:(r+8,2t) c3:(r+8,2t+1)
#pragma unroll
    for (int fm = 0; fm < 4; fm++) {
#pragma unroll
        for (int fn = 0; fn < 4; fn++) {
            int gr = bm + wm * 64 + fm * 16 + r;
            int gc = bn + wn * 32 + fn * 8 + 2 * t;
            float bv0 = bias[gc], bv1 = bias[gc + 1];
            if (gr < Nn) {
                float2 o0 = make_float2(acc[fm][fn][0] + bv0, acc[fm][fn][1] + bv1);
                *(float2*)(C + (size_t)gr * Dd + gc) = o0;
            }
            if (gr + 8 < Nn) {
                float2 o1 = make_float2(acc[fm][fn][2] + bv0, acc[fm][fn][3] + bv1);
                *(float2*)(C + (size_t)(gr + 8) * Dd + gc) = o1;
            }
        }
    }
}

// ---------------- 5: edge scores + z + wv scatter (one warp per edge) ----------------
__global__ void k_edge(const int* __restrict__ src, const int* __restrict__ dst) {
    int gw = (blockIdx.x * blockDim.x + threadIdx.x) >> 5;
    int lane = threadIdx.x & 31;
    if (gw >= Ee) return;
    int s0 = src[gw], d0 = dst[gw];
    const float4* kr = (const float4*)(g_k + (size_t)s0 * Dd);
    const float4* qr = (const float4*)(g_q + (size_t)d0 * Dd);
    float4 a0 = kr[lane * 2], a1 = kr[lane * 2 + 1];
    float4 b0 = qr[lane * 2], b1 = qr[lane * 2 + 1];
    float dot = a0.x * b0.x + a0.y * b0.y + a0.z * b0.z + a0.w * b0.w +
                a1.x * b1.x + a1.y * b1.y + a1.z * b1.z + a1.w * b1.w;
    dot += __shfl_down_sync(0xffffffffu, dot, 4, 8);
    dot += __shfl_down_sync(0xffffffffu, dot, 2, 8);
    dot += __shfl_down_sync(0xffffffffu, dot, 1, 8);
    float sv = 0.0f;
    if ((lane & 7) == 0) {
        float sc = fminf(fmaxf(dot * 0.125f, -5.0f), 5.0f);
        sv = expf(sc);
        atomicAdd(&g_z[d0 * Hh + (lane >> 3)], sv);
    }
    sv = __shfl_sync(0xffffffffu, sv, 0, 8);
    const float4* vr = (const float4*)(g_vv + (size_t)s0 * Dd);
    float4 v0 = vr[lane * 2], v1 = vr[lane * 2 + 1];
    float* wout = g_wv + (size_t)d0 * Dd + lane * 8;
    asm volatile("red.global.add.v4.f32 [%0], {%1,%2,%3,%4};"
                 :: "l"(wout), "f"(v0.x * sv), "f"(v0.y * sv),
                    "f"(v0.z * sv), "f"(v0.w * sv) : "memory");
    asm volatile("red.global.add.v4.f32 [%0], {%1,%2,%3,%4};"
                 :: "l"(wout + 4), "f"(v1.x * sv), "f"(v1.y * sv),
                    "f"(v1.z * sv), "f"(v1.w * sv) : "memory");
}

// ---------------- 6: BatchNorm column statistics ----------------
__global__ void k_bnstat() {
    int t = threadIdx.x;
    int r0 = blockIdx.x * 40;
    float s = 0.0f, ss = 0.0f;
    for (int r = r0; r < r0 + 40; r++) {
        float val = g_o[(size_t)r * Dd + t];
        s += val;
        ss = fmaf(val, val, ss);
    }
    atomicAdd(&g_bnsum[t], s);
    atomicAdd(&g_bnss[t], ss);
}

// ---------------- 7: fused BN + ReLU6 + SE + hardswish + residual ----------------
__global__ void __launch_bounds__(256) k_se(const float* __restrict__ gamma,
                                            const float* __restrict__ beta,
                                            const float* __restrict__ W1,
                                            const float* __restrict__ b1,
                                            const float* __restrict__ W2,
                                            const float* __restrict__ b2,
                                            const float* __restrict__ v,
                                            float* __restrict__ out) {
    __shared__ float xs[16][256];
    __shared__ float hs[16][64];
    __shared__ float sa[256], sb[256];
    int t = threadIdx.x;
    int row0 = blockIdx.x * 16;

    {
        float mean = g_bnsum[t] * (1.0f / Nn);
        float var = g_bnss[t] * (1.0f / Nn) - mean * mean;
        float istd = rsqrtf(var + BN_EPS);
        float a = gamma[t] * istd;
        sa[t] = a;
        sb[t] = beta[t] - mean * a;
    }
    __syncthreads();

    for (int i = t; i < 16 * 256; i += 256) {
        int r = i >> 8, c = i & 255;
        float xv = fmaf(sa[c], g_o[(size_t)(row0 + r) * Dd + c], sb[c]);
        xs[r][c] = fminf(fmaxf(xv, 0.0f), 6.0f);
    }
    __syncthreads();

    {
        int hc = t & 63, rg = t >> 6;
        float acc0 = b1[hc], acc1 = acc0, acc2 = acc0, acc3 = acc0;
        for (int k = 0; k < 256; k++) {
            float w = W1[k * 64 + hc];
            acc0 = fmaf(xs[rg * 4 + 0][k], w, acc0);
            acc1 = fmaf(xs[rg * 4 + 1][k], w, acc1);
            acc2 = fmaf(xs[rg * 4 + 2][k], w, acc2);
            acc3 = fmaf(xs[rg * 4 + 3][k], w, acc3);
        }
        hs[rg * 4 + 0][hc] = fminf(fmaxf(acc0, 0.0f), 6.0f);
        hs[rg * 4 + 1][hc] = fminf(fmaxf(acc1, 0.0f), 6.0f);
        hs[rg * 4 + 2][hc] = fminf(fmaxf(acc2, 0.0f), 6.0f);
        hs[rg * 4 + 3][hc] = fminf(fmaxf(acc3, 0.0f), 6.0f);
    }
    __syncthreads();

    {
        int col = t;
        float acc[16];
        float bb = b2[col];
#pragma unroll
        for (int r = 0; r < 16; r++) acc[r] = bb;
        for (int k = 0; k < 64; k++) {
            float w = W2[k * 256 + col];
#pragma unroll
            for (int r = 0; r < 16; r++) acc[r] = fmaf(hs[r][k], w, acc[r]);
        }
#pragma unroll
        for (int r = 0; r < 16; r++) {
            float u = acc[r];
            float act = u * __saturatef((u + 3.0f) * (1.0f / 6.0f));
            size_t idx = (size_t)(row0 + r) * Dd + col;
            out[idx] = fmaf(act, xs[r][col], v[idx]);
        }
    }
}

// ---------------- launch ----------------
extern "C" void kernel_launch(void* const* d_in, const int* in_sizes, int n_in,
                              void* d_out, int out_size) {
    const float* v     = (const float*)d_in[0];
    const float* WQ    = (const float*)d_in[1];
    const float* bQ    = (const float*)d_in[2];
    const float* WK    = (const float*)d_in[3];
    const float* bK    = (const float*)d_in[4];
    const float* WV    = (const float*)d_in[5];
    const float* bV    = (const float*)d_in[6];
    const float* Wo    = (const float*)d_in[7];
    const float* bo    = (const float*)d_in[8];
    const float* W1    = (const float*)d_in[9];
    const float* b1    = (const float*)d_in[10];
    const float* W2    = (const float*)d_in[11];
    const float* b2    = (const float*)d_in[12];
    const float* gamma = (const float*)d_in[13];
    const float* beta  = (const float*)d_in[14];
    const int*   src   = (const int*)d_in[15];
    const int*   dst   = (const int*)d_in[16];
    float* out = (float*)d_out;

    k_zero<<<(Nn * Dd + 255) / 256, 256>>>();
    k_degree<<<(Ee + 255) / 256, 256>>>(src, dst);
    k_softmax_reduce<<<1, 1024>>>();
    k_mvT<<<dim3(8, 316), dim3(32, 8)>>>(v);

    k_gemm_tc<0><<<dim3(2, 79, 3), 256>>>(WQ, WK, WV, bQ, bK, bV);

    k_edge<<<(Ee * 32 + 255) / 256, 256>>>(src, dst);
    k_wvT<<<dim3(8, 316), dim3(32, 8)>>>();

    k_gemm_tc<1><<<dim3(2, 79, 1), 256>>>(Wo, nullptr, nullptr, bo, nullptr, nullptr);

    k_bnstat<<<Nn / 40, 256>>>();
    k_se<<<Nn / 16, 256>>>(gamma, beta, W1, b1, W2, b2, v, out);
}

// round 3
// speedup vs baseline: 3.0606x; 1.1043x over previous
#include <cuda_runtime.h>
#include <math.h>

#define Nn 10000
#define Ee 320000
#define Dd 256
#define Hh 4
#define BN_EPS 1e-5f
#define MPAD 10112   // 79 * 128, padded row length for transposed activations

// ---------------- scratch (device globals) ----------------
__device__ float g_deg[Nn];
__device__ int   g_cnt[Nn];
__device__ int   g_off[Nn + 1];
__device__ int   g_fill[Nn];
__device__ int   g_csrc[Ee];
__device__ float g_smax;
__device__ float g_ssum;
__device__ float g_mVT[Dd * MPAD];   // transposed, center-scaled mV
__device__ float g_q[Nn * Dd];
__device__ float g_k[Nn * Dd];
__device__ float g_vv[Nn * Dd];
__device__ float g_wvT[Dd * MPAD];   // transposed wv / z
__device__ float g_o[Nn * Dd];
__device__ float g_bnsum[Dd];
__device__ float g_bnss[Dd];

// ---------------- 0: zero scratch ----------------
__global__ void k_zero() {
    int i = blockIdx.x * blockDim.x + threadIdx.x;
    if (i < Nn) { g_deg[i] = 0.0f; g_cnt[i] = 0; }
    if (i < Dd) { g_bnsum[i] = 0.0f; g_bnss[i] = 0.0f; }
}

// ---------------- 1: degree counts (+ dst histogram for CSR) ----------------
__global__ void k_degree(const int* __restrict__ src, const int* __restrict__ dst) {
    int e = blockIdx.x * blockDim.x + threadIdx.x;
    if (e < Ee) {
        int s = src[e], d = dst[e];
        atomicAdd(&g_deg[s], 1.0f);
        atomicAdd(&g_deg[d], 1.0f);
        atomicAdd(&g_cnt[d], 1);
    }
}

// ---------------- 1b: exclusive scan of g_cnt -> g_off / g_fill ----------------
__global__ void k_scan() {
    __shared__ int partial[1024];
    const int PER = 10;
    int t = threadIdx.x;
    int base = t * PER;
    int local[PER];
    int s = 0;
#pragma unroll
    for (int i = 0; i < PER; i++) {
        int idx = base + i;
        int c = (idx < Nn) ? g_cnt[idx] : 0;
        local[i] = s;
        s += c;
    }
    partial[t] = s;
    __syncthreads();
    for (int off = 1; off < 1024; off <<= 1) {
        int v = (t >= off) ? partial[t - off] : 0;
        __syncthreads();
        partial[t] += v;
        __syncthreads();
    }
    int pre = (t > 0) ? partial[t - 1] : 0;
#pragma unroll
    for (int i = 0; i < PER; i++) {
        int idx = base + i;
        if (idx < Nn) {
            int o = pre + local[i];
            g_off[idx] = o;
            g_fill[idx] = o;
        }
    }
    if (t == 0) g_off[Nn] = Ee;
}

// ---------------- 1c: scatter src ids into CSR order ----------------
__global__ void k_scatter(const int* __restrict__ src, const int* __restrict__ dst) {
    int e = blockIdx.x * blockDim.x + threadIdx.x;
    if (e < Ee) {
        int d = dst[e];
        int pos = atomicAdd(&g_fill[d], 1);
        g_csrc[pos] = src[e];
    }
}

// ---------------- 2: softmax(deg) reduction ----------------
__global__ void k_softmax_reduce() {
    __shared__ float red[1024];
    int t = threadIdx.x;
    float m = -1e30f;
    for (int i = t; i < Nn; i += 1024) m = fmaxf(m, g_deg[i]);
    red[t] = m; __syncthreads();
    for (int s = 512; s > 0; s >>= 1) {
        if (t < s) red[t] = fmaxf(red[t], red[t + s]);
        __syncthreads();
    }
    float gm = red[0];
    __syncthreads();
    float sum = 0.0f;
    for (int i = t; i < Nn; i += 1024) sum += expf(g_deg[i] - gm);
    red[t] = sum; __syncthreads();
    for (int s = 512; s > 0; s >>= 1) {
        if (t < s) red[t] += red[t + s];
        __syncthreads();
    }
    if (t == 0) { g_smax = gm; g_ssum = red[0]; }
}

// ---------------- 3: mVT[d][n] = v[n][d] * center[n]  (float4 transpose) ----------------
__global__ void k_mvT(const float* __restrict__ v) {
    __shared__ float tile[32][33];
    int d0 = blockIdx.x * 32;
    int n0 = blockIdx.y * 32;
    int tx = threadIdx.x;   // 0..7 (d / 4)
    int ty = threadIdx.y;   // 0..31 (n)
    int n = n0 + ty;
    float4 a = make_float4(0.f, 0.f, 0.f, 0.f);
    if (n < Nn) {
        float c = expf(g_deg[n] - g_smax) / g_ssum;
        a = *(const float4*)(v + (size_t)n * Dd + d0 + tx * 4);
        a.x *= c; a.y *= c; a.z *= c; a.w *= c;
    }
    tile[tx * 4 + 0][ty] = a.x;
    tile[tx * 4 + 1][ty] = a.y;
    tile[tx * 4 + 2][ty] = a.z;
    tile[tx * 4 + 3][ty] = a.w;
    __syncthreads();
    // write: thread (tx,ty) -> d = d0+ty, n-chunk = tx*4
    float4 o;
    o.x = tile[ty][tx * 4 + 0];
    o.y = tile[ty][tx * 4 + 1];
    o.z = tile[ty][tx * 4 + 2];
    o.w = tile[ty][tx * 4 + 3];
    *(float4*)(g_mVT + (size_t)(d0 + ty) * MPAD + n0 + tx * 4) = o;
}

// ---------------- tf32 helpers ----------------
__device__ __forceinline__ unsigned cvt_tf32(float f) {
    unsigned u;
    asm("cvt.rna.tf32.f32 %0, %1;" : "=r"(u) : "f"(f));
    return u;
}

__device__ __forceinline__ void mma8(float* c, const unsigned* a, const unsigned* b) {
    asm volatile(
        "mma.sync.aligned.m16n8k8.row.col.f32.tf32.tf32.f32 "
        "{%0,%1,%2,%3},{%4,%5,%6,%7},{%8,%9},{%0,%1,%2,%3};"
        : "+f"(c[0]), "+f"(c[1]), "+f"(c[2]), "+f"(c[3])
        : "r"(a[0]), "r"(a[1]), "r"(a[2]), "r"(a[3]), "r"(b[0]), "r"(b[1]));
}

// ---------------- 4: tf32 tensor-core GEMM ----------------
template <int MODE>
__global__ void __launch_bounds__(256) k_gemm_tc(
    const float* __restrict__ Wa, const float* __restrict__ Wb, const float* __restrict__ Wc,
    const float* __restrict__ ba, const float* __restrict__ bb, const float* __restrict__ bc) {
    const float* AT;
    const float* W;
    const float* bias;
    float* C;
    if (MODE == 0) {
        AT = g_mVT;
        int z = blockIdx.z;
        W = (z == 0) ? Wa : (z == 1) ? Wb : Wc;
        bias = (z == 0) ? ba : (z == 1) ? bb : bc;
        C = (z == 0) ? g_q : (z == 1) ? g_k : g_vv;
    } else {
        AT = g_wvT; W = Wa; bias = ba; C = g_o;
    }

    __shared__ unsigned As[32][136];
    __shared__ unsigned Bs[32][136];

    const int tid = threadIdx.x;
    const int lane = tid & 31;
    const int warp = tid >> 5;
    const int wm = warp & 1;
    const int wn = warp >> 1;
    const int bm = blockIdx.y * 128;
    const int bn = blockIdx.x * 128;
    const int r = lane >> 2;
    const int t = lane & 3;

    float acc[4][4][4];
#pragma unroll
    for (int i = 0; i < 4; i++)
#pragma unroll
        for (int j = 0; j < 4; j++)
#pragma unroll
            for (int q = 0; q < 4; q++) acc[i][j][q] = 0.0f;

    for (int k0 = 0; k0 < Dd; k0 += 32) {
#pragma unroll
        for (int i = 0; i < 4; i++) {
            int idx = tid + i * 256;
            int kr = idx >> 5;
            int mc = (idx & 31) << 2;
            float4 a = *(const float4*)(AT + (size_t)(k0 + kr) * MPAD + bm + mc);
            uint4 ua;
            ua.x = cvt_tf32(a.x); ua.y = cvt_tf32(a.y);
            ua.z = cvt_tf32(a.z); ua.w = cvt_tf32(a.w);
            *(uint4*)&As[kr][mc] = ua;
            float4 b = *(const float4*)(W + (size_t)(k0 + kr) * Dd + bn + mc);
            uint4 ub;
            ub.x = cvt_tf32(b.x); ub.y = cvt_tf32(b.y);
            ub.z = cvt_tf32(b.z); ub.w = cvt_tf32(b.w);
            *(uint4*)&Bs[kr][mc] = ub;
        }
        __syncthreads();
#pragma unroll
        for (int kk = 0; kk < 32; kk += 8) {
            unsigned af[4][4];
#pragma unroll
            for (int fm = 0; fm < 4; fm++) {
                int m = wm * 64 + fm * 16 + r;
                af[fm][0] = As[kk + t][m];
                af[fm][1] = As[kk + t][m + 8];
                af[fm][2] = As[kk + t + 4][m];
                af[fm][3] = As[kk + t + 4][m + 8];
            }
            unsigned bf[4][2];
#pragma unroll
            for (int fn = 0; fn < 4; fn++) {
                int n = wn * 32 + fn * 8 + r;
                bf[fn][0] = Bs[kk + t][n];
                bf[fn][1] = Bs[kk + t + 4][n];
            }
#pragma unroll
            for (int fm = 0; fm < 4; fm++)
#pragma unroll
                for (int fn = 0; fn < 4; fn++)
                    mma8(acc[fm][fn], af[fm], bf[fn]);
        }
        __syncthreads();
    }

#pragma unroll
    for (int fm = 0; fm < 4; fm++) {
#pragma unroll
        for (int fn = 0; fn < 4; fn++) {
            int gr = bm + wm * 64 + fm * 16 + r;
            int gc = bn + wn * 32 + fn * 8 + 2 * t;
            float bv0 = bias[gc], bv1 = bias[gc + 1];
            if (gr < Nn) {
                float2 o0 = make_float2(acc[fm][fn][0] + bv0, acc[fm][fn][1] + bv1);
                *(float2*)(C + (size_t)gr * Dd + gc) = o0;
            }
            if (gr + 8 < Nn) {
                float2 o1 = make_float2(acc[fm][fn][2] + bv0, acc[fm][fn][3] + bv1);
                *(float2*)(C + (size_t)(gr + 8) * Dd + gc) = o1;
            }
        }
    }
}

// ---------------- 5: CSR aggregation: one warp per dst node, no atomics ----------------
// Writes wvT (transposed, z-normalized) directly via smem transpose staging.
__global__ void __launch_bounds__(256) k_agg() {
    __shared__ float xp[32][264];   // [local n][d]
    int tid = threadIdx.x;
    int lane = tid & 31;
    int w = tid >> 5;
    int n0 = blockIdx.x * 32;
    int grp0 = lane & ~7;           // base lane of 8-lane head group

#pragma unroll 1
    for (int i = 0; i < 4; i++) {
        int ln = w * 4 + i;
        int n = n0 + ln;
        float4 accA = make_float4(0.f, 0.f, 0.f, 0.f);
        float4 accB = make_float4(0.f, 0.f, 0.f, 0.f);
        if (n < Nn) {
            const float4* qr = (const float4*)(g_q + (size_t)n * Dd);
            float4 q0 = qr[lane * 2], q1 = qr[lane * 2 + 1];
            float z = 0.0f;
            int e = g_off[n];
            int end = g_off[n + 1];
            // 2-edge unrolled main loop
            for (; e + 2 <= end; e += 2) {
                int s0 = g_csrc[e], s1 = g_csrc[e + 1];
                const float4* kr0 = (const float4*)(g_k + (size_t)s0 * Dd);
                const float4* kr1 = (const float4*)(g_k + (size_t)s1 * Dd);
                float4 a0 = kr0[lane * 2], a1 = kr0[lane * 2 + 1];
                float4 c0 = kr1[lane * 2], c1 = kr1[lane * 2 + 1];
                float d0 = a0.x * q0.x + a0.y * q0.y + a0.z * q0.z + a0.w * q0.w +
                           a1.x * q1.x + a1.y * q1.y + a1.z * q1.z + a1.w * q1.w;
                float d1 = c0.x * q0.x + c0.y * q0.y + c0.z * q0.z + c0.w * q0.w +
                           c1.x * q1.x + c1.y * q1.y + c1.z * q1.z + c1.w * q1.w;
                d0 += __shfl_down_sync(0xffffffffu, d0, 4, 8);
                d1 += __shfl_down_sync(0xffffffffu, d1, 4, 8);
                d0 += __shfl_down_sync(0xffffffffu, d0, 2, 8);
                d1 += __shfl_down_sync(0xffffffffu, d1, 2, 8);
                d0 += __shfl_down_sync(0xffffffffu, d0, 1, 8);
                d1 += __shfl_down_sync(0xffffffffu, d1, 1, 8);
                d0 = __shfl_sync(0xffffffffu, d0, grp0);
                d1 = __shfl_sync(0xffffffffu, d1, grp0);
                float sv0 = __expf(fminf(fmaxf(d0 * 0.125f, -5.0f), 5.0f));
                float sv1 = __expf(fminf(fmaxf(d1 * 0.125f, -5.0f), 5.0f));
                z += sv0 + sv1;
                const float4* vr0 = (const float4*)(g_vv + (size_t)s0 * Dd);
                const float4* vr1 = (const float4*)(g_vv + (size_t)s1 * Dd);
                float4 v0 = vr0[lane * 2], v1 = vr0[lane * 2 + 1];
                float4 u0 = vr1[lane * 2], u1 = vr1[lane * 2 + 1];
                accA.x = fmaf(v0.x, sv0, accA.x); accA.y = fmaf(v0.y, sv0, accA.y);
                accA.z = fmaf(v0.z, sv0, accA.z); accA.w = fmaf(v0.w, sv0, accA.w);
                accB.x = fmaf(v1.x, sv0, accB.x); accB.y = fmaf(v1.y, sv0, accB.y);
                accB.z = fmaf(v1.z, sv0, accB.z); accB.w = fmaf(v1.w, sv0, accB.w);
                accA.x = fmaf(u0.x, sv1, accA.x); accA.y = fmaf(u0.y, sv1, accA.y);
                accA.z = fmaf(u0.z, sv1, accA.z); accA.w = fmaf(u0.w, sv1, accA.w);
                accB.x = fmaf(u1.x, sv1, accB.x); accB.y = fmaf(u1.y, sv1, accB.y);
                accB.z = fmaf(u1.z, sv1, accB.z); accB.w = fmaf(u1.w, sv1, accB.w);
            }
            if (e < end) {
                int s0 = g_csrc[e];
                const float4* kr0 = (const float4*)(g_k + (size_t)s0 * Dd);
                float4 a0 = kr0[lane * 2], a1 = kr0[lane * 2 + 1];
                float d0 = a0.x * q0.x + a0.y * q0.y + a0.z * q0.z + a0.w * q0.w +
                           a1.x * q1.x + a1.y * q1.y + a1.z * q1.z + a1.w * q1.w;
                d0 += __shfl_down_sync(0xffffffffu, d0, 4, 8);
                d0 += __shfl_down_sync(0xffffffffu, d0, 2, 8);
                d0 += __shfl_down_sync(0xffffffffu, d0, 1, 8);
                d0 = __shfl_sync(0xffffffffu, d0, grp0);
                float sv0 = __expf(fminf(fmaxf(d0 * 0.125f, -5.0f), 5.0f));
                z += sv0;
                const float4* vr0 = (const float4*)(g_vv + (size_t)s0 * Dd);
                float4 v0 = vr0[lane * 2], v1 = vr0[lane * 2 + 1];
                accA.x = fmaf(v0.x, sv0, accA.x); accA.y = fmaf(v0.y, sv0, accA.y);
                accA.z = fmaf(v0.z, sv0, accA.z); accA.w = fmaf(v0.w, sv0, accA.w);
                accB.x = fmaf(v1.x, sv0, accB.x); accB.y = fmaf(v1.y, sv0, accB.y);
                accB.z = fmaf(v1.z, sv0, accB.z); accB.w = fmaf(v1.w, sv0, accB.w);
            }
            float inv = 1.0f / z;
            accA.x *= inv; accA.y *= inv; accA.z *= inv; accA.w *= inv;
            accB.x *= inv; accB.y *= inv; accB.z *= inv; accB.w *= inv;
        }
        *(float4*)&xp[ln][lane * 8] = accA;
        *(float4*)&xp[ln][lane * 8 + 4] = accB;
    }
    __syncthreads();
    // transpose out: 8 consecutive threads cover 32 n at one d
#pragma unroll
    for (int rep = 0; rep < 8; rep++) {
        int d = (tid >> 3) + rep * 32;
        int nc = (tid & 7) * 4;
        float4 o;
        o.x = xp[nc + 0][d];
        o.y = xp[nc + 1][d];
        o.z = xp[nc + 2][d];
        o.w = xp[nc + 3][d];
        *(float4*)(g_wvT + (size_t)d * MPAD + n0 + nc) = o;
    }
}

// ---------------- 6: BatchNorm column statistics ----------------
__global__ void k_bnstat() {
    int t = threadIdx.x;
    int r0 = blockIdx.x * 40;
    float s = 0.0f, ss = 0.0f;
    for (int r = r0; r < r0 + 40; r++) {
        float val = g_o[(size_t)r * Dd + t];
        s += val;
        ss = fmaf(val, val, ss);
    }
    atomicAdd(&g_bnsum[t], s);
    atomicAdd(&g_bnss[t], ss);
}

// ---------------- 7: fused BN + ReLU6 + SE + hardswish + residual ----------------
__global__ void __launch_bounds__(256) k_se(const float* __restrict__ gamma,
                                            const float* __restrict__ beta,
                                            const float* __restrict__ W1,
                                            const float* __restrict__ b1,
                                            const float* __restrict__ W2,
                                            const float* __restrict__ b2,
                                            const float* __restrict__ v,
                                            float* __restrict__ out) {
    __shared__ float xs[16][256];
    __shared__ float hs[16][64];
    __shared__ float sa[256], sb[256];
    int t = threadIdx.x;
    int row0 = blockIdx.x * 16;

    {
        float mean = g_bnsum[t] * (1.0f / Nn);
        float var = g_bnss[t] * (1.0f / Nn) - mean * mean;
        float istd = rsqrtf(var + BN_EPS);
        float a = gamma[t] * istd;
        sa[t] = a;
        sb[t] = beta[t] - mean * a;
    }
    __syncthreads();

    for (int i = t; i < 16 * 256; i += 256) {
        int r = i >> 8, c = i & 255;
        float xv = fmaf(sa[c], g_o[(size_t)(row0 + r) * Dd + c], sb[c]);
        xs[r][c] = fminf(fmaxf(xv, 0.0f), 6.0f);
    }
    __syncthreads();

    {
        int hc = t & 63, rg = t >> 6;
        float acc0 = b1[hc], acc1 = acc0, acc2 = acc0, acc3 = acc0;
        for (int k = 0; k < 256; k++) {
            float w = W1[k * 64 + hc];
            acc0 = fmaf(xs[rg * 4 + 0][k], w, acc0);
            acc1 = fmaf(xs[rg * 4 + 1][k], w, acc1);
            acc2 = fmaf(xs[rg * 4 + 2][k], w, acc2);
            acc3 = fmaf(xs[rg * 4 + 3][k], w, acc3);
        }
        hs[rg * 4 + 0][hc] = fminf(fmaxf(acc0, 0.0f), 6.0f);
        hs[rg * 4 + 1][hc] = fminf(fmaxf(acc1, 0.0f), 6.0f);
        hs[rg * 4 + 2][hc] = fminf(fmaxf(acc2, 0.0f), 6.0f);
        hs[rg * 4 + 3][hc] = fminf(fmaxf(acc3, 0.0f), 6.0f);
    }
    __syncthreads();

    {
        int col = t;
        float acc[16];
        float bb = b2[col];
#pragma unroll
        for (int r = 0; r < 16; r++) acc[r] = bb;
        for (int k = 0; k < 64; k++) {
            float w = W2[k * 256 + col];
#pragma unroll
            for (int r = 0; r < 16; r++) acc[r] = fmaf(hs[r][k], w, acc[r]);
        }
#pragma unroll
        for (int r = 0; r < 16; r++) {
            float u = acc[r];
            float act = u * __saturatef((u + 3.0f) * (1.0f / 6.0f));
            size_t idx = (size_t)(row0 + r) * Dd + col;
            out[idx] = fmaf(act, xs[r][col], v[idx]);
        }
    }
}

// ---------------- launch ----------------
extern "C" void kernel_launch(void* const* d_in, const int* in_sizes, int n_in,
                              void* d_out, int out_size) {
    const float* v     = (const float*)d_in[0];
    const float* WQ    = (const float*)d_in[1];
    const float* bQ    = (const float*)d_in[2];
    const float* WK    = (const float*)d_in[3];
    const float* bK    = (const float*)d_in[4];
    const float* WV    = (const float*)d_in[5];
    const float* bV    = (const float*)d_in[6];
    const float* Wo    = (const float*)d_in[7];
    const float* bo    = (const float*)d_in[8];
    const float* W1    = (const float*)d_in[9];
    const float* b1    = (const float*)d_in[10];
    const float* W2    = (const float*)d_in[11];
    const float* b2    = (const float*)d_in[12];
    const float* gamma = (const float*)d_in[13];
    const float* beta  = (const float*)d_in[14];
    const int*   src   = (const int*)d_in[15];
    const int*   dst   = (const int*)d_in[16];
    float* out = (float*)d_out;

    k_zero<<<(Nn + 255) / 256, 256>>>();
    k_degree<<<(Ee + 255) / 256, 256>>>(src, dst);
    k_scan<<<1, 1024>>>();
    k_scatter<<<(Ee + 255) / 256, 256>>>(src, dst);
    k_softmax_reduce<<<1, 1024>>>();
    k_mvT<<<dim3(8, 316), dim3(8, 32)>>>(v);

    k_gemm_tc<0><<<dim3(2, 79, 3), 256>>>(WQ, WK, WV, bQ, bK, bV);

    k_agg<<<316, 256>>>();

    k_gemm_tc<1><<<dim3(2, 79, 1), 256>>>(Wo, nullptr, nullptr, bo, nullptr, nullptr);

    k_bnstat<<<Nn / 40, 256>>>();
    k_se<<<Nn / 16, 256>>>(gamma, beta, W1, b1, W2, b2, v, out);
}

// round 4
// speedup vs baseline: 3.7208x; 1.2157x over previous
#include <cuda_runtime.h>
#include <cuda_bf16.h>
#include <math.h>

#define Nn 10000
#define Ee 320000
#define Dd 256
#define Hh 4
#define BN_EPS 1e-5f
#define MPAD 10112   // 79 * 128, padded row length for transposed activations

// ---------------- scratch (device globals) ----------------
__device__ float g_deg[Nn];
__device__ int   g_cnt[Nn];
__device__ int   g_off[Nn + 1];
__device__ int   g_fill[Nn];
__device__ int   g_csrc[Ee];
__device__ float g_smax;
__device__ float g_ssum;
__device__ float g_mVT[Dd * MPAD];           // transposed, center-scaled mV
__device__ float g_q[Nn * Dd];               // fp32 q
__device__ __nv_bfloat162 g_kh[Nn * (Dd/2)]; // bf16 k
__device__ __nv_bfloat162 g_vh[Nn * (Dd/2)]; // bf16 vv
__device__ float g_wvT[Dd * MPAD];           // transposed wv / z
__device__ float g_o[Nn * Dd];
__device__ float g_bnsum[Dd];
__device__ float g_bnss[Dd];

// ---------------- 0: zero scratch ----------------
__global__ void k_zero() {
    int i = blockIdx.x * blockDim.x + threadIdx.x;
    if (i < Nn) { g_deg[i] = 0.0f; g_cnt[i] = 0; }
    if (i < Dd) { g_bnsum[i] = 0.0f; g_bnss[i] = 0.0f; }
}

// ---------------- 1: degree counts (+ dst histogram for CSR) ----------------
__global__ void k_degree(const int* __restrict__ src, const int* __restrict__ dst) {
    int e = blockIdx.x * blockDim.x + threadIdx.x;
    if (e < Ee) {
        int s = src[e], d = dst[e];
        atomicAdd(&g_deg[s], 1.0f);
        atomicAdd(&g_deg[d], 1.0f);
        atomicAdd(&g_cnt[d], 1);
    }
}

// ---------------- 1b: exclusive scan of g_cnt + softmax(deg) reduction ----------------
__global__ void k_scan_softmax() {
    __shared__ int partial[1024];
    __shared__ float red[1024];
    const int PER = 10;
    int t = threadIdx.x;
    int base = t * PER;
    int local[PER];
    int s = 0;
#pragma unroll
    for (int i = 0; i < PER; i++) {
        int idx = base + i;
        int c = (idx < Nn) ? g_cnt[idx] : 0;
        local[i] = s;
        s += c;
    }
    partial[t] = s;
    __syncthreads();
    for (int off = 1; off < 1024; off <<= 1) {
        int v = (t >= off) ? partial[t - off] : 0;
        __syncthreads();
        partial[t] += v;
        __syncthreads();
    }
    int pre = (t > 0) ? partial[t - 1] : 0;
#pragma unroll
    for (int i = 0; i < PER; i++) {
        int idx = base + i;
        if (idx < Nn) {
            int o = pre + local[i];
            g_off[idx] = o;
            g_fill[idx] = o;
        }
    }
    if (t == 0) g_off[Nn] = Ee;

    // softmax(deg): max then sum-of-exp
    float m = -1e30f;
    for (int i = t; i < Nn; i += 1024) m = fmaxf(m, g_deg[i]);
    red[t] = m; __syncthreads();
    for (int st = 512; st > 0; st >>= 1) {
        if (t < st) red[t] = fmaxf(red[t], red[t + st]);
        __syncthreads();
    }
    float gm = red[0];
    __syncthreads();
    float sum = 0.0f;
    for (int i = t; i < Nn; i += 1024) sum += expf(g_deg[i] - gm);
    red[t] = sum; __syncthreads();
    for (int st = 512; st > 0; st >>= 1) {
        if (t < st) red[t] += red[t + st];
        __syncthreads();
    }
    if (t == 0) { g_smax = gm; g_ssum = red[0]; }
}

// ---------------- 1c: scatter src ids into CSR order ----------------
__global__ void k_scatter(const int* __restrict__ src, const int* __restrict__ dst) {
    int e = blockIdx.x * blockDim.x + threadIdx.x;
    if (e < Ee) {
        int d = dst[e];
        int pos = atomicAdd(&g_fill[d], 1);
        g_csrc[pos] = src[e];
    }
}

// ---------------- 3: mVT[d][n] = v[n][d] * center[n]  (float4 transpose) ----------------
__global__ void k_mvT(const float* __restrict__ v) {
    __shared__ float tile[32][33];
    int d0 = blockIdx.x * 32;
    int n0 = blockIdx.y * 32;
    int tx = threadIdx.x;   // 0..7 (d / 4)
    int ty = threadIdx.y;   // 0..31 (n)
    int n = n0 + ty;
    float4 a = make_float4(0.f, 0.f, 0.f, 0.f);
    if (n < Nn) {
        float c = expf(g_deg[n] - g_smax) / g_ssum;
        a = *(const float4*)(v + (size_t)n * Dd + d0 + tx * 4);
        a.x *= c; a.y *= c; a.z *= c; a.w *= c;
    }
    tile[tx * 4 + 0][ty] = a.x;
    tile[tx * 4 + 1][ty] = a.y;
    tile[tx * 4 + 2][ty] = a.z;
    tile[tx * 4 + 3][ty] = a.w;
    __syncthreads();
    float4 o;
    o.x = tile[ty][tx * 4 + 0];
    o.y = tile[ty][tx * 4 + 1];
    o.z = tile[ty][tx * 4 + 2];
    o.w = tile[ty][tx * 4 + 3];
    *(float4*)(g_mVT + (size_t)(d0 + ty) * MPAD + n0 + tx * 4) = o;
}

// ---------------- tf32 helpers ----------------
__device__ __forceinline__ unsigned cvt_tf32(float f) {
    unsigned u;
    asm("cvt.rna.tf32.f32 %0, %1;" : "=r"(u) : "f"(f));
    return u;
}

__device__ __forceinline__ void mma8(float* c, const unsigned* a, const unsigned* b) {
    asm volatile(
        "mma.sync.aligned.m16n8k8.row.col.f32.tf32.tf32.f32 "
        "{%0,%1,%2,%3},{%4,%5,%6,%7},{%8,%9},{%0,%1,%2,%3};"
        : "+f"(c[0]), "+f"(c[1]), "+f"(c[2]), "+f"(c[3])
        : "r"(a[0]), "r"(a[1]), "r"(a[2]), "r"(a[3]), "r"(b[0]), "r"(b[1]));
}

// ---------------- 4: tf32 tensor-core GEMM ----------------
// MODE 0: A = mVT; z=0 -> g_q (fp32), z=1 -> g_kh (bf16), z=2 -> g_vh (bf16)
// MODE 1: A = wvT -> g_o (fp32)
template <int MODE>
__global__ void __launch_bounds__(256) k_gemm_tc(
    const float* __restrict__ Wa, const float* __restrict__ Wb, const float* __restrict__ Wc,
    const float* __restrict__ ba, const float* __restrict__ bb, const float* __restrict__ bc) {
    const float* AT;
    const float* W;
    const float* bias;
    int zsel = 0;
    if (MODE == 0) {
        AT = g_mVT;
        zsel = blockIdx.z;
        W = (zsel == 0) ? Wa : (zsel == 1) ? Wb : Wc;
        bias = (zsel == 0) ? ba : (zsel == 1) ? bb : bc;
    } else {
        AT = g_wvT; W = Wa; bias = ba;
    }

    __shared__ unsigned As[32][136];
    __shared__ unsigned Bs[32][136];

    const int tid = threadIdx.x;
    const int lane = tid & 31;
    const int warp = tid >> 5;
    const int wm = warp & 1;
    const int wn = warp >> 1;
    const int bm = blockIdx.y * 128;
    const int bn = blockIdx.x * 128;
    const int r = lane >> 2;
    const int t = lane & 3;

    float acc[4][4][4];
#pragma unroll
    for (int i = 0; i < 4; i++)
#pragma unroll
        for (int j = 0; j < 4; j++)
#pragma unroll
            for (int q = 0; q < 4; q++) acc[i][j][q] = 0.0f;

    for (int k0 = 0; k0 < Dd; k0 += 32) {
#pragma unroll
        for (int i = 0; i < 4; i++) {
            int idx = tid + i * 256;
            int kr = idx >> 5;
            int mc = (idx & 31) << 2;
            float4 a = *(const float4*)(AT + (size_t)(k0 + kr) * MPAD + bm + mc);
            uint4 ua;
            ua.x = cvt_tf32(a.x); ua.y = cvt_tf32(a.y);
            ua.z = cvt_tf32(a.z); ua.w = cvt_tf32(a.w);
            *(uint4*)&As[kr][mc] = ua;
            float4 b = *(const float4*)(W + (size_t)(k0 + kr) * Dd + bn + mc);
            uint4 ub;
            ub.x = cvt_tf32(b.x); ub.y = cvt_tf32(b.y);
            ub.z = cvt_tf32(b.z); ub.w = cvt_tf32(b.w);
            *(uint4*)&Bs[kr][mc] = ub;
        }
        __syncthreads();
#pragma unroll
        for (int kk = 0; kk < 32; kk += 8) {
            unsigned af[4][4];
#pragma unroll
            for (int fm = 0; fm < 4; fm++) {
                int m = wm * 64 + fm * 16 + r;
                af[fm][0] = As[kk + t][m];
                af[fm][1] = As[kk + t][m + 8];
                af[fm][2] = As[kk + t + 4][m];
                af[fm][3] = As[kk + t + 4][m + 8];
            }
            unsigned bf[4][2];
#pragma unroll
            for (int fn = 0; fn < 4; fn++) {
                int n = wn * 32 + fn * 8 + r;
                bf[fn][0] = Bs[kk + t][n];
                bf[fn][1] = Bs[kk + t + 4][n];
            }
#pragma unroll
            for (int fm = 0; fm < 4; fm++)
#pragma unroll
                for (int fn = 0; fn < 4; fn++)
                    mma8(acc[fm][fn], af[fm], bf[fn]);
        }
        __syncthreads();
    }

#pragma unroll
    for (int fm = 0; fm < 4; fm++) {
#pragma unroll
        for (int fn = 0; fn < 4; fn++) {
            int gr = bm + wm * 64 + fm * 16 + r;
            int gc = bn + wn * 32 + fn * 8 + 2 * t;
            float bv0 = bias[gc], bv1 = bias[gc + 1];
            float2 o0 = make_float2(acc[fm][fn][0] + bv0, acc[fm][fn][1] + bv1);
            float2 o1 = make_float2(acc[fm][fn][2] + bv0, acc[fm][fn][3] + bv1);
            if (MODE == 1 || zsel == 0) {
                float* C = (MODE == 1) ? g_o : g_q;
                if (gr < Nn)     *(float2*)(C + (size_t)gr * Dd + gc) = o0;
                if (gr + 8 < Nn) *(float2*)(C + (size_t)(gr + 8) * Dd + gc) = o1;
            } else {
                __nv_bfloat162* Ch = (zsel == 1) ? g_kh : g_vh;
                if (gr < Nn)     Ch[(size_t)gr * (Dd/2) + (gc >> 1)] = __float22bfloat162_rn(o0);
                if (gr + 8 < Nn) Ch[(size_t)(gr + 8) * (Dd/2) + (gc >> 1)] = __float22bfloat162_rn(o1);
            }
        }
    }
}

// ---------------- bf16 dot helper: 8 dims (one uint4) vs fp32 q ----------------
__device__ __forceinline__ float dot8(uint4 kx, float4 q0, float4 q1) {
    float2 p0 = __bfloat1622float2(*(__nv_bfloat162*)&kx.x);
    float2 p1 = __bfloat1622float2(*(__nv_bfloat162*)&kx.y);
    float2 p2 = __bfloat1622float2(*(__nv_bfloat162*)&kx.z);
    float2 p3 = __bfloat1622float2(*(__nv_bfloat162*)&kx.w);
    float d = p0.x * q0.x;
    d = fmaf(p0.y, q0.y, d);
    d = fmaf(p1.x, q0.z, d);
    d = fmaf(p1.y, q0.w, d);
    d = fmaf(p2.x, q1.x, d);
    d = fmaf(p2.y, q1.y, d);
    d = fmaf(p3.x, q1.z, d);
    d = fmaf(p3.y, q1.w, d);
    return d;
}

__device__ __forceinline__ void fma8(float4& a, float4& b, uint4 vx, float s) {
    float2 p0 = __bfloat1622float2(*(__nv_bfloat162*)&vx.x);
    float2 p1 = __bfloat1622float2(*(__nv_bfloat162*)&vx.y);
    float2 p2 = __bfloat1622float2(*(__nv_bfloat162*)&vx.z);
    float2 p3 = __bfloat1622float2(*(__nv_bfloat162*)&vx.w);
    a.x = fmaf(p0.x, s, a.x); a.y = fmaf(p0.y, s, a.y);
    a.z = fmaf(p1.x, s, a.z); a.w = fmaf(p1.y, s, a.w);
    b.x = fmaf(p2.x, s, b.x); b.y = fmaf(p2.y, s, b.y);
    b.z = fmaf(p3.x, s, b.z); b.w = fmaf(p3.y, s, b.w);
}

// ---------------- 5: CSR aggregation: one warp per node, bf16 gathers, 4-edge MLP ----------
__global__ void __launch_bounds__(256) k_agg() {
    __shared__ float xp[8][264];   // [local n][d]
    int tid = threadIdx.x;
    int lane = tid & 31;
    int w = tid >> 5;
    int n0 = blockIdx.x * 8;
    int n = n0 + w;
    int grp0 = lane & ~7;          // base lane of 8-lane head group

    const float4* qr = (const float4*)(g_q + (size_t)n * Dd);
    float4 q0 = qr[lane * 2], q1 = qr[lane * 2 + 1];
    float4 accA = make_float4(0.f, 0.f, 0.f, 0.f);
    float4 accB = make_float4(0.f, 0.f, 0.f, 0.f);
    float z = 0.0f;
    int e = g_off[n];
    const int end = g_off[n + 1];
    const char* kbase = (const char*)g_kh;
    const char* vbase = (const char*)g_vh;
    const size_t loff = (size_t)lane * 16;

    for (; e + 4 <= end; e += 4) {
        int s0 = g_csrc[e], s1 = g_csrc[e + 1], s2 = g_csrc[e + 2], s3 = g_csrc[e + 3];
        uint4 k0 = *(const uint4*)(kbase + (size_t)s0 * 512 + loff);
        uint4 k1 = *(const uint4*)(kbase + (size_t)s1 * 512 + loff);
        uint4 k2 = *(const uint4*)(kbase + (size_t)s2 * 512 + loff);
        uint4 k3 = *(const uint4*)(kbase + (size_t)s3 * 512 + loff);
        uint4 v0 = *(const uint4*)(vbase + (size_t)s0 * 512 + loff);
        uint4 v1 = *(const uint4*)(vbase + (size_t)s1 * 512 + loff);
        uint4 v2 = *(const uint4*)(vbase + (size_t)s2 * 512 + loff);
        uint4 v3 = *(const uint4*)(vbase + (size_t)s3 * 512 + loff);
        float d0 = dot8(k0, q0, q1);
        float d1 = dot8(k1, q0, q1);
        float d2 = dot8(k2, q0, q1);
        float d3 = dot8(k3, q0, q1);
        d0 += __shfl_down_sync(0xffffffffu, d0, 4, 8);
        d1 += __shfl_down_sync(0xffffffffu, d1, 4, 8);
        d2 += __shfl_down_sync(0xffffffffu, d2, 4, 8);
        d3 += __shfl_down_sync(0xffffffffu, d3, 4, 8);
        d0 += __shfl_down_sync(0xffffffffu, d0, 2, 8);
        d1 += __shfl_down_sync(0xffffffffu, d1, 2, 8);
        d2 += __shfl_down_sync(0xffffffffu, d2, 2, 8);
        d3 += __shfl_down_sync(0xffffffffu, d3, 2, 8);
        d0 += __shfl_down_sync(0xffffffffu, d0, 1, 8);
        d1 += __shfl_down_sync(0xffffffffu, d1, 1, 8);
        d2 += __shfl_down_sync(0xffffffffu, d2, 1, 8);
        d3 += __shfl_down_sync(0xffffffffu, d3, 1, 8);
        d0 = __shfl_sync(0xffffffffu, d0, grp0);
        d1 = __shfl_sync(0xffffffffu, d1, grp0);
        d2 = __shfl_sync(0xffffffffu, d2, grp0);
        d3 = __shfl_sync(0xffffffffu, d3, grp0);
        float sv0 = __expf(fminf(fmaxf(d0 * 0.125f, -5.0f), 5.0f));
        float sv1 = __expf(fminf(fmaxf(d1 * 0.125f, -5.0f), 5.0f));
        float sv2 = __expf(fminf(fmaxf(d2 * 0.125f, -5.0f), 5.0f));
        float sv3 = __expf(fminf(fmaxf(d3 * 0.125f, -5.0f), 5.0f));
        z += (sv0 + sv1) + (sv2 + sv3);
        fma8(accA, accB, v0, sv0);
        fma8(accA, accB, v1, sv1);
        fma8(accA, accB, v2, sv2);
        fma8(accA, accB, v3, sv3);
    }
    for (; e < end; e++) {
        int s0 = g_csrc[e];
        uint4 k0 = *(const uint4*)(kbase + (size_t)s0 * 512 + loff);
        uint4 v0 = *(const uint4*)(vbase + (size_t)s0 * 512 + loff);
        float d0 = dot8(k0, q0, q1);
        d0 += __shfl_down_sync(0xffffffffu, d0, 4, 8);
        d0 += __shfl_down_sync(0xffffffffu, d0, 2, 8);
        d0 += __shfl_down_sync(0xffffffffu, d0, 1, 8);
        d0 = __shfl_sync(0xffffffffu, d0, grp0);
        float sv0 = __expf(fminf(fmaxf(d0 * 0.125f, -5.0f), 5.0f));
        z += sv0;
        fma8(accA, accB, v0, sv0);
    }
    float inv = 1.0f / z;
    accA.x *= inv; accA.y *= inv; accA.z *= inv; accA.w *= inv;
    accB.x *= inv; accB.y *= inv; accB.z *= inv; accB.w *= inv;
    *(float4*)&xp[w][lane * 8] = accA;
    *(float4*)&xp[w][lane * 8 + 4] = accB;
    __syncthreads();

    // transpose out: thread t -> dim d = t, 8 nodes
    int d = tid;
    float4 oA, oB;
    oA.x = xp[0][d]; oA.y = xp[1][d]; oA.z = xp[2][d]; oA.w = xp[3][d];
    oB.x = xp[4][d]; oB.y = xp[5][d]; oB.z = xp[6][d]; oB.w = xp[7][d];
    *(float4*)(g_wvT + (size_t)d * MPAD + n0)     = oA;
    *(float4*)(g_wvT + (size_t)d * MPAD + n0 + 4) = oB;
}

// ---------------- 6: BatchNorm column statistics ----------------
__global__ void k_bnstat() {
    int t = threadIdx.x;
    int r0 = blockIdx.x * 40;
    float s = 0.0f, ss = 0.0f;
    for (int r = r0; r < r0 + 40; r++) {
        float val = g_o[(size_t)r * Dd + t];
        s += val;
        ss = fmaf(val, val, ss);
    }
    atomicAdd(&g_bnsum[t], s);
    atomicAdd(&g_bnss[t], ss);
}

// ---------------- 7: fused BN + ReLU6 + SE + hardswish + residual ----------------
__global__ void __launch_bounds__(256) k_se(const float* __restrict__ gamma,
                                            const float* __restrict__ beta,
                                            const float* __restrict__ W1,
                                            const float* __restrict__ b1,
                                            const float* __restrict__ W2,
                                            const float* __restrict__ b2,
                                            const float* __restrict__ v,
                                            float* __restrict__ out) {
    __shared__ float xs[16][256];
    __shared__ float hs[16][64];
    __shared__ float sa[256], sb[256];
    int t = threadIdx.x;
    int row0 = blockIdx.x * 16;

    {
        float mean = g_bnsum[t] * (1.0f / Nn);
        float var = g_bnss[t] * (1.0f / Nn) - mean * mean;
        float istd = rsqrtf(var + BN_EPS);
        float a = gamma[t] * istd;
        sa[t] = a;
        sb[t] = beta[t] - mean * a;
    }
    __syncthreads();

    for (int i = t; i < 16 * 256; i += 256) {
        int r = i >> 8, c = i & 255;
        float xv = fmaf(sa[c], g_o[(size_t)(row0 + r) * Dd + c], sb[c]);
        xs[r][c] = fminf(fmaxf(xv, 0.0f), 6.0f);
    }
    __syncthreads();

    {
        int hc = t & 63, rg = t >> 6;
        float acc0 = b1[hc], acc1 = acc0, acc2 = acc0, acc3 = acc0;
        for (int k = 0; k < 256; k++) {
            float w = W1[k * 64 + hc];
            acc0 = fmaf(xs[rg * 4 + 0][k], w, acc0);
            acc1 = fmaf(xs[rg * 4 + 1][k], w, acc1);
            acc2 = fmaf(xs[rg * 4 + 2][k], w, acc2);
            acc3 = fmaf(xs[rg * 4 + 3][k], w, acc3);
        }
        hs[rg * 4 + 0][hc] = fminf(fmaxf(acc0, 0.0f), 6.0f);
        hs[rg * 4 + 1][hc] = fminf(fmaxf(acc1, 0.0f), 6.0f);
        hs[rg * 4 + 2][hc] = fminf(fmaxf(acc2, 0.0f), 6.0f);
        hs[rg * 4 + 3][hc] = fminf(fmaxf(acc3, 0.0f), 6.0f);
    }
    __syncthreads();

    {
        int col = t;
        float acc[16];
        float bb = b2[col];
#pragma unroll
        for (int r = 0; r < 16; r++) acc[r] = bb;
        for (int k = 0; k < 64; k++) {
            float w = W2[k * 256 + col];
#pragma unroll
            for (int r = 0; r < 16; r++) acc[r] = fmaf(hs[r][k], w, acc[r]);
        }
#pragma unroll
        for (int r = 0; r < 16; r++) {
            float u = acc[r];
            float act = u * __saturatef((u + 3.0f) * (1.0f / 6.0f));
            size_t idx = (size_t)(row0 + r) * Dd + col;
            out[idx] = fmaf(act, xs[r][col], v[idx]);
        }
    }
}

// ---------------- launch ----------------
extern "C" void kernel_launch(void* const* d_in, const int* in_sizes, int n_in,
                              void* d_out, int out_size) {
    const float* v     = (const float*)d_in[0];
    const float* WQ    = (const float*)d_in[1];
    const float* bQ    = (const float*)d_in[2];
    const float* WK    = (const float*)d_in[3];
    const float* bK    = (const float*)d_in[4];
    const float* WV    = (const float*)d_in[5];
    const float* bV    = (const float*)d_in[6];
    const float* Wo    = (const float*)d_in[7];
    const float* bo    = (const float*)d_in[8];
    const float* W1    = (const float*)d_in[9];
    const float* b1    = (const float*)d_in[10];
    const float* W2    = (const float*)d_in[11];
    const float* b2    = (const float*)d_in[12];
    const float* gamma = (const float*)d_in[13];
    const float* beta  = (const float*)d_in[14];
    const int*   src   = (const int*)d_in[15];
    const int*   dst   = (const int*)d_in[16];
    float* out = (float*)d_out;

    k_zero<<<(Nn + 255) / 256, 256>>>();
    k_degree<<<(Ee + 255) / 256, 256>>>(src, dst);
    k_scan_softmax<<<1, 1024>>>();
    k_scatter<<<(Ee + 255) / 256, 256>>>(src, dst);
    k_mvT<<<dim3(8, 316), dim3(8, 32)>>>(v);

    k_gemm_tc<0><<<dim3(2, 79, 3), 256>>>(WQ, WK, WV, bQ, bK, bV);

    k_agg<<<1250, 256>>>();

    k_gemm_tc<1><<<dim3(2, 79, 1), 256>>>(Wo, nullptr, nullptr, bo, nullptr, nullptr);

    k_bnstat<<<Nn / 40, 256>>>();
    k_se<<<Nn / 16, 256>>>(gamma, beta, W1, b1, W2, b2, v, out);
}

// round 5
// speedup vs baseline: 4.3924x; 1.1805x over previous
#include <cuda_runtime.h>
#include <cuda_bf16.h>
#include <math.h>

#define Nn 10000
#define Ee 320000
#define Dd 256
#define Hh 4
#define BN_EPS 1e-5f
#define MROWS 10112   // 79 * 128 padded rows

// ---------------- scratch (device globals) ----------------
__device__ float g_deg[Nn];
__device__ int   g_cnt[Nn];
__device__ int   g_off[Nn + 1];
__device__ int   g_fill[Nn];
__device__ int   g_csrc[Ee];
__device__ float g_smax;
__device__ float g_ssum;
__device__ __nv_bfloat16 g_mVh[MROWS * Dd];  // bf16 center-scaled mV (row-major)
__device__ float g_q[MROWS * Dd];            // fp32 q
__device__ __nv_bfloat16 g_kh[MROWS * Dd];   // bf16 k
__device__ __nv_bfloat16 g_vh[MROWS * Dd];   // bf16 vv
__device__ __nv_bfloat16 g_wv[MROWS * Dd];   // bf16 normalized wv (row-major)
__device__ float g_o[MROWS * Dd];
__device__ __nv_bfloat16 g_Wth[4 * Dd * Dd]; // bf16 transposed weights [z][n][k]
__device__ float g_bnsum[Dd];
__device__ float g_bnss[Dd];

// ---------------- 0: zero scratch ----------------
__global__ void k_zero() {
    int i = blockIdx.x * blockDim.x + threadIdx.x;
    if (i < Nn) { g_deg[i] = 0.0f; g_cnt[i] = 0; }
    if (i < Dd) { g_bnsum[i] = 0.0f; g_bnss[i] = 0.0f; }
}

// ---------------- 1: degree counts (+ dst histogram for CSR) ----------------
__global__ void k_degree(const int* __restrict__ src, const int* __restrict__ dst) {
    int e = blockIdx.x * blockDim.x + threadIdx.x;
    if (e < Ee) {
        int s = src[e], d = dst[e];
        atomicAdd(&g_deg[s], 1.0f);
        atomicAdd(&g_deg[d], 1.0f);
        atomicAdd(&g_cnt[d], 1);
    }
}

// ---------------- 1b: exclusive scan of g_cnt + softmax(deg) reduction ----------------
__global__ void k_scan_softmax() {
    __shared__ int partial[1024];
    __shared__ float red[1024];
    const int PER = 10;
    int t = threadIdx.x;
    int base = t * PER;
    int local[PER];
    int s = 0;
#pragma unroll
    for (int i = 0; i < PER; i++) {
        int idx = base + i;
        int c = (idx < Nn) ? g_cnt[idx] : 0;
        local[i] = s;
        s += c;
    }
    partial[t] = s;
    __syncthreads();
    for (int off = 1; off < 1024; off <<= 1) {
        int v = (t >= off) ? partial[t - off] : 0;
        __syncthreads();
        partial[t] += v;
        __syncthreads();
    }
    int pre = (t > 0) ? partial[t - 1] : 0;
#pragma unroll
    for (int i = 0; i < PER; i++) {
        int idx = base + i;
        if (idx < Nn) {
            int o = pre + local[i];
            g_off[idx] = o;
            g_fill[idx] = o;
        }
    }
    if (t == 0) g_off[Nn] = Ee;

    float m = -1e30f;
    for (int i = t; i < Nn; i += 1024) m = fmaxf(m, g_deg[i]);
    red[t] = m; __syncthreads();
    for (int st = 512; st > 0; st >>= 1) {
        if (t < st) red[t] = fmaxf(red[t], red[t + st]);
        __syncthreads();
    }
    float gm = red[0];
    __syncthreads();
    float sum = 0.0f;
    for (int i = t; i < Nn; i += 1024) sum += expf(g_deg[i] - gm);
    red[t] = sum; __syncthreads();
    for (int st = 512; st > 0; st >>= 1) {
        if (t < st) red[t] += red[t + st];
        __syncthreads();
    }
    if (t == 0) { g_smax = gm; g_ssum = red[0]; }
}

// ---------------- 1c: scatter src ids into CSR order ----------------
__global__ void k_scatter(const int* __restrict__ src, const int* __restrict__ dst) {
    int e = blockIdx.x * blockDim.x + threadIdx.x;
    if (e < Ee) {
        int d = dst[e];
        int pos = atomicAdd(&g_fill[d], 1);
        g_csrc[pos] = src[e];
    }
}

// ---------------- 2: mVh[n][d] = bf16(v[n][d] * center[n]) ----------------
__global__ void k_mv(const float* __restrict__ v) {
    int i4 = blockIdx.x * blockDim.x + threadIdx.x;
    if (i4 >= Nn * Dd / 4) return;
    int n = i4 >> 6;
    float c = expf(g_deg[n] - g_smax) / g_ssum;
    float4 a = ((const float4*)v)[i4];
    __nv_bfloat162 p0 = __float22bfloat162_rn(make_float2(a.x * c, a.y * c));
    __nv_bfloat162 p1 = __float22bfloat162_rn(make_float2(a.z * c, a.w * c));
    __nv_bfloat162* o = (__nv_bfloat162*)g_mVh;
    o[i4 * 2]     = p0;
    o[i4 * 2 + 1] = p1;
}

// ---------------- 2b: transpose weights to bf16 Wt[z][n][k] ----------------
__global__ void k_wt(const float* __restrict__ WQ, const float* __restrict__ WK,
                     const float* __restrict__ WV, const float* __restrict__ Wo) {
    __shared__ float t[32][33];
    int z = blockIdx.z;
    const float* W = (z == 0) ? WQ : (z == 1) ? WK : (z == 2) ? WV : Wo;
    int k0 = blockIdx.x * 32, n0 = blockIdx.y * 32;
    int tx = threadIdx.x, ty = threadIdx.y;
#pragma unroll
    for (int j = 0; j < 32; j += 8)
        t[ty + j][tx] = W[(size_t)(k0 + ty + j) * Dd + n0 + tx];
    __syncthreads();
#pragma unroll
    for (int j = 0; j < 32; j += 8)
        g_Wth[(size_t)z * Dd * Dd + (size_t)(n0 + ty + j) * Dd + k0 + tx] =
            __float2bfloat16(t[tx][ty + j]);
}

// ---------------- cp.async helpers ----------------
__device__ __forceinline__ void cpa16(void* s, const void* g) {
    unsigned sa = (unsigned)__cvta_generic_to_shared(s);
    asm volatile("cp.async.ca.shared.global [%0], [%1], 16;" :: "r"(sa), "l"(g));
}
__device__ __forceinline__ void cp_commit() { asm volatile("cp.async.commit_group;"); }
__device__ __forceinline__ void cp_wait1() { asm volatile("cp.async.wait_group 1;"); }

__device__ __forceinline__ void mma16(float* c, const unsigned* a, const unsigned* b) {
    asm volatile(
        "mma.sync.aligned.m16n8k16.row.col.f32.bf16.bf16.f32 "
        "{%0,%1,%2,%3},{%4,%5,%6,%7},{%8,%9},{%0,%1,%2,%3};"
        : "+f"(c[0]), "+f"(c[1]), "+f"(c[2]), "+f"(c[3])
        : "r"(a[0]), "r"(a[1]), "r"(a[2]), "r"(a[3]), "r"(b[0]), "r"(b[1]));
}

// ---------------- 4: bf16 tensor-core GEMM, cp.async double-buffered --------------
// MODE 0: A = g_mVh; z=0 -> g_q (fp32), z=1 -> g_kh, z=2 -> g_vh
// MODE 1: A = g_wv -> g_o (fp32), weight slab 3
template <int MODE>
__global__ void __launch_bounds__(256) k_gemm_bf16(
    const float* __restrict__ ba, const float* __restrict__ bb, const float* __restrict__ bc) {
    __shared__ __nv_bfloat16 As[2][128 * 40];
    __shared__ __nv_bfloat16 Bs[2][128 * 40];

    const int zsel = (MODE == 0) ? blockIdx.z : 3;
    const __nv_bfloat16* A = (MODE == 0) ? g_mVh : g_wv;
    const __nv_bfloat16* B = g_Wth + (size_t)zsel * Dd * Dd;
    const float* bias = (MODE == 1) ? ba : (zsel == 0) ? ba : (zsel == 1) ? bb : bc;

    const int tid = threadIdx.x;
    const int lane = tid & 31;
    const int warp = tid >> 5;
    const int wm = warp & 1;
    const int wn = warp >> 1;
    const int gid = lane >> 2;
    const int tig = lane & 3;
    const int bm = blockIdx.y * 128;
    const int bn = blockIdx.x * 128;

    const int lrow0 = tid >> 2;              // chunk rows for cp.async
    const int lcol0 = (tid & 3) * 8;
    const int lrow1 = (tid + 256) >> 2;
    const int lcol1 = lcol0;

    float acc[4][4][4];
#pragma unroll
    for (int i = 0; i < 4; i++)
#pragma unroll
        for (int j = 0; j < 4; j++)
#pragma unroll
            for (int q = 0; q < 4; q++) acc[i][j][q] = 0.0f;

    // prologue: stage 0
    {
        cpa16(&As[0][lrow0 * 40 + lcol0], A + (size_t)(bm + lrow0) * Dd + lcol0);
        cpa16(&As[0][lrow1 * 40 + lcol1], A + (size_t)(bm + lrow1) * Dd + lcol1);
        cpa16(&Bs[0][lrow0 * 40 + lcol0], B + (size_t)(bn + lrow0) * Dd + lcol0);
        cpa16(&Bs[0][lrow1 * 40 + lcol1], B + (size_t)(bn + lrow1) * Dd + lcol1);
    }
    cp_commit();

    for (int ks = 0; ks < 8; ks++) {
        if (ks < 7) {
            int st = (ks + 1) & 1;
            int k0 = (ks + 1) * 32;
            cpa16(&As[st][lrow0 * 40 + lcol0], A + (size_t)(bm + lrow0) * Dd + k0 + lcol0);
            cpa16(&As[st][lrow1 * 40 + lcol1], A + (size_t)(bm + lrow1) * Dd + k0 + lcol1);
            cpa16(&Bs[st][lrow0 * 40 + lcol0], B + (size_t)(bn + lrow0) * Dd + k0 + lcol0);
            cpa16(&Bs[st][lrow1 * 40 + lcol1], B + (size_t)(bn + lrow1) * Dd + k0 + lcol1);
        }
        cp_commit();
        cp_wait1();
        __syncthreads();
        const __nv_bfloat16* as = As[ks & 1];
        const __nv_bfloat16* bs = Bs[ks & 1];
#pragma unroll
        for (int kk = 0; kk < 2; kk++) {
            int kb = kk * 16 + 2 * tig;
            unsigned af[4][4];
#pragma unroll
            for (int fm = 0; fm < 4; fm++) {
                int m = wm * 64 + fm * 16 + gid;
                af[fm][0] = *(const unsigned*)&as[m * 40 + kb];
                af[fm][1] = *(const unsigned*)&as[(m + 8) * 40 + kb];
                af[fm][2] = *(const unsigned*)&as[m * 40 + kb + 8];
                af[fm][3] = *(const unsigned*)&as[(m + 8) * 40 + kb + 8];
            }
            unsigned bfr[4][2];
#pragma unroll
            for (int fn = 0; fn < 4; fn++) {
                int n = wn * 32 + fn * 8 + gid;
                bfr[fn][0] = *(const unsigned*)&bs[n * 40 + kb];
                bfr[fn][1] = *(const unsigned*)&bs[n * 40 + kb + 8];
            }
#pragma unroll
            for (int fm = 0; fm < 4; fm++)
#pragma unroll
                for (int fn = 0; fn < 4; fn++)
                    mma16(acc[fm][fn], af[fm], bfr[fn]);
        }
        __syncthreads();
    }

    // epilogue (buffers padded to MROWS -> no row guards)
#pragma unroll
    for (int fm = 0; fm < 4; fm++) {
#pragma unroll
        for (int fn = 0; fn < 4; fn++) {
            int gr = bm + wm * 64 + fm * 16 + gid;
            int gc = bn + wn * 32 + fn * 8 + 2 * tig;
            float bv0 = bias[gc], bv1 = bias[gc + 1];
            float2 o0 = make_float2(acc[fm][fn][0] + bv0, acc[fm][fn][1] + bv1);
            float2 o1 = make_float2(acc[fm][fn][2] + bv0, acc[fm][fn][3] + bv1);
            if (MODE == 1 || zsel == 0) {
                float* C = (MODE == 1) ? g_o : g_q;
                *(float2*)(C + (size_t)gr * Dd + gc) = o0;
                *(float2*)(C + (size_t)(gr + 8) * Dd + gc) = o1;
            } else {
                __nv_bfloat162* Ch = (__nv_bfloat162*)((zsel == 1) ? g_kh : g_vh);
                Ch[(size_t)gr * (Dd / 2) + (gc >> 1)] = __float22bfloat162_rn(o0);
                Ch[(size_t)(gr + 8) * (Dd / 2) + (gc >> 1)] = __float22bfloat162_rn(o1);
            }
        }
    }
}

// ---------------- bf16 helpers for aggregation ----------------
__device__ __forceinline__ float dot8(uint4 kx, float4 q0, float4 q1) {
    float2 p0 = __bfloat1622float2(*(__nv_bfloat162*)&kx.x);
    float2 p1 = __bfloat1622float2(*(__nv_bfloat162*)&kx.y);
    float2 p2 = __bfloat1622float2(*(__nv_bfloat162*)&kx.z);
    float2 p3 = __bfloat1622float2(*(__nv_bfloat162*)&kx.w);
    float d = p0.x * q0.x;
    d = fmaf(p0.y, q0.y, d);
    d = fmaf(p1.x, q0.z, d);
    d = fmaf(p1.y, q0.w, d);
    d = fmaf(p2.x, q1.x, d);
    d = fmaf(p2.y, q1.y, d);
    d = fmaf(p3.x, q1.z, d);
    d = fmaf(p3.y, q1.w, d);
    return d;
}

__device__ __forceinline__ void fma8(float4& a, float4& b, uint4 vx, float s) {
    float2 p0 = __bfloat1622float2(*(__nv_bfloat162*)&vx.x);
    float2 p1 = __bfloat1622float2(*(__nv_bfloat162*)&vx.y);
    float2 p2 = __bfloat1622float2(*(__nv_bfloat162*)&vx.z);
    float2 p3 = __bfloat1622float2(*(__nv_bfloat162*)&vx.w);
    a.x = fmaf(p0.x, s, a.x); a.y = fmaf(p0.y, s, a.y);
    a.z = fmaf(p1.x, s, a.z); a.w = fmaf(p1.y, s, a.w);
    b.x = fmaf(p2.x, s, b.x); b.y = fmaf(p2.y, s, b.y);
    b.z = fmaf(p3.x, s, b.z); b.w = fmaf(p3.y, s, b.w);
}

// ---------------- 5: CSR aggregation: one warp per node, emits bf16 wv row --------
__global__ void __launch_bounds__(256) k_agg() {
    int tid = threadIdx.x;
    int lane = tid & 31;
    int w = tid >> 5;
    int n = blockIdx.x * 8 + w;
    int grp0 = lane & ~7;

    const float4* qr = (const float4*)(g_q + (size_t)n * Dd);
    float4 q0 = qr[lane * 2], q1 = qr[lane * 2 + 1];
    float4 accA = make_float4(0.f, 0.f, 0.f, 0.f);
    float4 accB = make_float4(0.f, 0.f, 0.f, 0.f);
    float z = 0.0f;
    int e = g_off[n];
    const int end = g_off[n + 1];
    const char* kbase = (const char*)g_kh;
    const char* vbase = (const char*)g_vh;
    const size_t loff = (size_t)lane * 16;

    for (; e + 4 <= end; e += 4) {
        int s0 = g_csrc[e], s1 = g_csrc[e + 1], s2 = g_csrc[e + 2], s3 = g_csrc[e + 3];
        uint4 k0 = *(const uint4*)(kbase + (size_t)s0 * 512 + loff);
        uint4 k1 = *(const uint4*)(kbase + (size_t)s1 * 512 + loff);
        uint4 k2 = *(const uint4*)(kbase + (size_t)s2 * 512 + loff);
        uint4 k3 = *(const uint4*)(kbase + (size_t)s3 * 512 + loff);
        uint4 v0 = *(const uint4*)(vbase + (size_t)s0 * 512 + loff);
        uint4 v1 = *(const uint4*)(vbase + (size_t)s1 * 512 + loff);
        uint4 v2 = *(const uint4*)(vbase + (size_t)s2 * 512 + loff);
        uint4 v3 = *(const uint4*)(vbase + (size_t)s3 * 512 + loff);
        float d0 = dot8(k0, q0, q1);
        float d1 = dot8(k1, q0, q1);
        float d2 = dot8(k2, q0, q1);
        float d3 = dot8(k3, q0, q1);
        d0 += __shfl_down_sync(0xffffffffu, d0, 4, 8);
        d1 += __shfl_down_sync(0xffffffffu, d1, 4, 8);
        d2 += __shfl_down_sync(0xffffffffu, d2, 4, 8);
        d3 += __shfl_down_sync(0xffffffffu, d3, 4, 8);
        d0 += __shfl_down_sync(0xffffffffu, d0, 2, 8);
        d1 += __shfl_down_sync(0xffffffffu, d1, 2, 8);
        d2 += __shfl_down_sync(0xffffffffu, d2, 2, 8);
        d3 += __shfl_down_sync(0xffffffffu, d3, 2, 8);
        d0 += __shfl_down_sync(0xffffffffu, d0, 1, 8);
        d1 += __shfl_down_sync(0xffffffffu, d1, 1, 8);
        d2 += __shfl_down_sync(0xffffffffu, d2, 1, 8);
        d3 += __shfl_down_sync(0xffffffffu, d3, 1, 8);
        d0 = __shfl_sync(0xffffffffu, d0, grp0);
        d1 = __shfl_sync(0xffffffffu, d1, grp0);
        d2 = __shfl_sync(0xffffffffu, d2, grp0);
        d3 = __shfl_sync(0xffffffffu, d3, grp0);
        float sv0 = __expf(fminf(fmaxf(d0 * 0.125f, -5.0f), 5.0f));
        float sv1 = __expf(fminf(fmaxf(d1 * 0.125f, -5.0f), 5.0f));
        float sv2 = __expf(fminf(fmaxf(d2 * 0.125f, -5.0f), 5.0f));
        float sv3 = __expf(fminf(fmaxf(d3 * 0.125f, -5.0f), 5.0f));
        z += (sv0 + sv1) + (sv2 + sv3);
        fma8(accA, accB, v0, sv0);
        fma8(accA, accB, v1, sv1);
        fma8(accA, accB, v2, sv2);
        fma8(accA, accB, v3, sv3);
    }
    for (; e < end; e++) {
        int s0 = g_csrc[e];
        uint4 k0 = *(const uint4*)(kbase + (size_t)s0 * 512 + loff);
        uint4 v0 = *(const uint4*)(vbase + (size_t)s0 * 512 + loff);
        float d0 = dot8(k0, q0, q1);
        d0 += __shfl_down_sync(0xffffffffu, d0, 4, 8);
        d0 += __shfl_down_sync(0xffffffffu, d0, 2, 8);
        d0 += __shfl_down_sync(0xffffffffu, d0, 1, 8);
        d0 = __shfl_sync(0xffffffffu, d0, grp0);
        float sv0 = __expf(fminf(fmaxf(d0 * 0.125f, -5.0f), 5.0f));
        z += sv0;
        fma8(accA, accB, v0, sv0);
    }
    float inv = 1.0f / z;
    uint4 pk;
    __nv_bfloat162 b0 = __float22bfloat162_rn(make_float2(accA.x * inv, accA.y * inv));
    __nv_bfloat162 b1 = __float22bfloat162_rn(make_float2(accA.z * inv, accA.w * inv));
    __nv_bfloat162 b2 = __float22bfloat162_rn(make_float2(accB.x * inv, accB.y * inv));
    __nv_bfloat162 b3 = __float22bfloat162_rn(make_float2(accB.z * inv, accB.w * inv));
    pk.x = *(unsigned*)&b0; pk.y = *(unsigned*)&b1;
    pk.z = *(unsigned*)&b2; pk.w = *(unsigned*)&b3;
    *(uint4*)((char*)g_wv + (size_t)n * 512 + loff) = pk;
}

// ---------------- 6: BatchNorm column statistics ----------------
__global__ void k_bnstat() {
    int t = threadIdx.x;
    int r0 = blockIdx.x * 40;
    float s = 0.0f, ss = 0.0f;
    for (int r = r0; r < r0 + 40; r++) {
        float val = g_o[(size_t)r * Dd + t];
        s += val;
        ss = fmaf(val, val, ss);
    }
    atomicAdd(&g_bnsum[t], s);
    atomicAdd(&g_bnss[t], ss);
}

// ---------------- 7: fused BN + ReLU6 + SE + hardswish + residual ----------------
__global__ void __launch_bounds__(256) k_se(const float* __restrict__ gamma,
                                            const float* __restrict__ beta,
                                            const float* __restrict__ W1,
                                            const float* __restrict__ b1,
                                            const float* __restrict__ W2,
                                            const float* __restrict__ b2,
                                            const float* __restrict__ v,
                                            float* __restrict__ out) {
    __shared__ float xs[16][256];
    __shared__ float hs[16][64];
    __shared__ float sa[256], sb[256];
    int t = threadIdx.x;
    int row0 = blockIdx.x * 16;

    {
        float mean = g_bnsum[t] * (1.0f / Nn);
        float var = g_bnss[t] * (1.0f / Nn) - mean * mean;
        float istd = rsqrtf(var + BN_EPS);
        float a = gamma[t] * istd;
        sa[t] = a;
        sb[t] = beta[t] - mean * a;
    }
    __syncthreads();

    for (int i = t; i < 16 * 256; i += 256) {
        int r = i >> 8, c = i & 255;
        float xv = fmaf(sa[c], g_o[(size_t)(row0 + r) * Dd + c], sb[c]);
        xs[r][c] = fminf(fmaxf(xv, 0.0f), 6.0f);
    }
    __syncthreads();

    {
        int hc = t & 63, rg = t >> 6;
        float acc0 = b1[hc], acc1 = acc0, acc2 = acc0, acc3 = acc0;
        for (int k = 0; k < 256; k++) {
            float w = W1[k * 64 + hc];
            acc0 = fmaf(xs[rg * 4 + 0][k], w, acc0);
            acc1 = fmaf(xs[rg * 4 + 1][k], w, acc1);
            acc2 = fmaf(xs[rg * 4 + 2][k], w, acc2);
            acc3 = fmaf(xs[rg * 4 + 3][k], w, acc3);
        }
        hs[rg * 4 + 0][hc] = fminf(fmaxf(acc0, 0.0f), 6.0f);
        hs[rg * 4 + 1][hc] = fminf(fmaxf(acc1, 0.0f), 6.0f);
        hs[rg * 4 + 2][hc] = fminf(fmaxf(acc2, 0.0f), 6.0f);
        hs[rg * 4 + 3][hc] = fminf(fmaxf(acc3, 0.0f), 6.0f);
    }
    __syncthreads();

    {
        int col = t;
        float acc[16];
        float bb = b2[col];
#pragma unroll
        for (int r = 0; r < 16; r++) acc[r] = bb;
        for (int k = 0; k < 64; k++) {
            float w = W2[k * 256 + col];
#pragma unroll
            for (int r = 0; r < 16; r++) acc[r] = fmaf(hs[r][k], w, acc[r]);
        }
#pragma unroll
        for (int r = 0; r < 16; r++) {
            float u = acc[r];
            float act = u * __saturatef((u + 3.0f) * (1.0f / 6.0f));
            size_t idx = (size_t)(row0 + r) * Dd + col;
            out[idx] = fmaf(act, xs[r][col], v[idx]);
        }
    }
}

// ---------------- launch ----------------
extern "C" void kernel_launch(void* const* d_in, const int* in_sizes, int n_in,
                              void* d_out, int out_size) {
    const float* v     = (const float*)d_in[0];
    const float* WQ    = (const float*)d_in[1];
    const float* bQ    = (const float*)d_in[2];
    const float* WK    = (const float*)d_in[3];
    const float* bK    = (const float*)d_in[4];
    const float* WV    = (const float*)d_in[5];
    const float* bV    = (const float*)d_in[6];
    const float* Wo    = (const float*)d_in[7];
    const float* bo    = (const float*)d_in[8];
    const float* W1    = (const float*)d_in[9];
    const float* b1    = (const float*)d_in[10];
    const float* W2    = (const float*)d_in[11];
    const float* b2    = (const float*)d_in[12];
    const float* gamma = (const float*)d_in[13];
    const float* beta  = (const float*)d_in[14];
    const int*   src   = (const int*)d_in[15];
    const int*   dst   = (const int*)d_in[16];
    float* out = (float*)d_out;

    k_zero<<<(Nn + 255) / 256, 256>>>();
    k_degree<<<(Ee + 255) / 256, 256>>>(src, dst);
    k_scan_softmax<<<1, 1024>>>();
    k_scatter<<<(Ee + 255) / 256, 256>>>(src, dst);
    k_wt<<<dim3(8, 8, 4), dim3(32, 8)>>>(WQ, WK, WV, Wo);
    k_mv<<<(Nn * Dd / 4 + 255) / 256, 256>>>(v);

    k_gemm_bf16<0><<<dim3(2, 79, 3), 256>>>(bQ, bK, bV);

    k_agg<<<1250, 256>>>();

    k_gemm_bf16<1><<<dim3(2, 79, 1), 256>>>(bo, nullptr, nullptr);

    k_bnstat<<<Nn / 40, 256>>>();
    k_se<<<Nn / 16, 256>>>(gamma, beta, W1, b1, W2, b2, v, out);
}